// round 14
// baseline (speedup 1.0000x reference)
#include <cuda_runtime.h>
#include <cuda_fp16.h>
#include <cstdint>

#define N_GRAPH   4096
#define NPG       32
#define N_NODES   (N_GRAPH * NPG)      // 131072
#define N_EDGES   (N_NODES * 16)       // 2097152
#define N_PAIRS   (N_EDGES / 2)        // 1048576
#define N_QUADS   (N_EDGES / 4)        // 524288
#define INV_SQRT3 0.57735026918962576451f
#define INV_SQRT2 0.70710678118654752440f
#define FULLM     0xFFFFFFFFu

#define NBINS     512
#define INV_DELTA 100.0f               // Δ = 0.01, domain [0, 5.11]

#define PB_BLOCKS 2048                 // pairs: 2048 x 2 chunks x 256
#define PB_CHUNKS 2
#define QB_BLOCKS 2048                 // quads: 2048 x 256 = N_QUADS

// ---------------- scratch (static device arrays) -----------------------------
__device__ int   g_cnt[N_NODES];
__device__ int   g_off[N_NODES + 1];
__device__ int   g_cur[N_NODES];
__device__ int   g_bs [256];
__device__ __align__(16) int g_rs [N_EDGES];      // receiver per sorted slot
__device__ __align__(16) float4 g_rec[N_EDGES];   // {dist, s_bits, h2(ux,uy), h2(uz,0)}

// radial tables
__device__ __align__(16) float g_tab1[NBINS * 8];   // R0[4] R1[4]
__device__ __align__(16) float g_tab2[NBINS * 20];  // R2..R6
__device__ __align__(16) float g_tab3[NBINS * 8];   // R7[4] R8[4]

__device__ __align__(16) float g_a0 [N_NODES * 4];
__device__ __align__(16) float g_a1 [N_NODES * 12];
__device__ __align__(16) __half g_xb[N_NODES * 16];
__device__ __align__(16) float g_b0 [N_NODES * 8];
__device__ __align__(16) float g_b1 [N_NODES * 36];
__device__ __align__(16) __half g_xc[N_NODES * 16];
__device__ __align__(16) float g_c0 [N_NODES * 8];

// ---------------- helpers ---------------------------------------------------
__device__ __forceinline__ void red4(float* p, float a, float b, float c, float d) {
    asm volatile("red.global.add.v4.f32 [%0], {%1,%2,%3,%4};"
                 :: "l"(p), "f"(a), "f"(b), "f"(c), "f"(d) : "memory");
}

__device__ __forceinline__ float sigmoidf(float x) {
    return 1.0f / (1.0f + __expf(-x));
}

__device__ __forceinline__ void unpack_rec(float4 rec, int& s, float& dist,
                                           float& ux, float& uy, float& uz) {
    dist = rec.x;
    s = __float_as_int(rec.y);
    __half2 xy = *reinterpret_cast<__half2*>(&rec.z);
    __half2 zp = *reinterpret_cast<__half2*>(&rec.w);
    float2 f = __half22float2(xy);
    ux = f.x; uy = f.y;
    uz = __half2float(__low2half(zp));
}

// exact radial (k_table only)
__device__ void radial_exact(int p, const float rbf[8], float R[4],
                             const float* w1g, const float* b1g,
                             const float* w2g, const float* b2g) {
    float h[8];
#pragma unroll
    for (int j = 0; j < 8; j++) h[j] = b1g[p*8 + j];
#pragma unroll
    for (int b = 0; b < 8; b++) {
        float rb = rbf[b];
#pragma unroll
        for (int j = 0; j < 8; j++) h[j] = fmaf(rb, w1g[p*64 + b*8 + j], h[j]);
    }
#pragma unroll
    for (int j = 0; j < 8; j++) h[j] = fmaxf(h[j], 0.0f);
#pragma unroll
    for (int c = 0; c < 4; c++) R[c] = b2g[p*4 + c];
#pragma unroll
    for (int j = 0; j < 8; j++) {
        float hj = h[j];
#pragma unroll
        for (int c = 0; c < 4; c++) R[c] = fmaf(hj, w2g[p*32 + j*4 + c], R[c]);
    }
}

__device__ __forceinline__ void lerp4(const float* st, int stride, int bin,
                                      float frac, int off, float R[4]) {
    float4 a = *reinterpret_cast<const float4*>(st + bin * stride + off);
    float4 b = *reinterpret_cast<const float4*>(st + (bin + 1) * stride + off);
    R[0] = fmaf(frac, b.x - a.x, a.x);
    R[1] = fmaf(frac, b.y - a.y, a.y);
    R[2] = fmaf(frac, b.z - a.z, a.z);
    R[3] = fmaf(frac, b.w - a.w, a.w);
}

__device__ __forceinline__ void bin_of(float dist, int& bin, float& frac) {
    float binf = dist * INV_DELTA;
    bin = min((int)binf, NBINS - 2);
    frac = fminf(binf - (float)bin, 1.0f);
}

__device__ __forceinline__ void store_packed16(__half* base, int n, const float* v) {
    uint4 pk[2];
    __half2* hp = reinterpret_cast<__half2*>(pk);
#pragma unroll
    for (int i = 0; i < 8; i++) hp[i] = __floats2half2_rn(v[2*i], v[2*i+1]);
    reinterpret_cast<uint4*>(base)[2*n+0] = pk[0];
    reinterpret_cast<uint4*>(base)[2*n+1] = pk[1];
}

__device__ __forceinline__ void load_packed16(const __half* base, int n, float* v) {
    uint4 pk[2];
    pk[0] = reinterpret_cast<const uint4*>(base)[2*n+0];
    pk[1] = reinterpret_cast<const uint4*>(base)[2*n+1];
    const __half2* hp = reinterpret_cast<const __half2*>(pk);
#pragma unroll
    for (int i = 0; i < 8; i++) {
        float2 f = __half22float2(hp[i]);
        v[2*i] = f.x; v[2*i+1] = f.y;
    }
}

__device__ __forceinline__ void unpack4(uint2 w, float o[4]) {
    float2 f0 = __half22float2(*reinterpret_cast<__half2*>(&w.x));
    float2 f1 = __half22float2(*reinterpret_cast<__half2*>(&w.y));
    o[0]=f0.x; o[1]=f0.y; o[2]=f1.x; o[3]=f1.y;
}

// segmented warp sum keyed by tail receiver
__device__ __forceinline__ void segred4(float v0, float v1, float v2, float v3,
                                        const bool p[5], bool head, float* addr) {
#pragma unroll
    for (int i = 0, off = 1; i < 5; i++, off <<= 1) {
        float t0 = __shfl_down_sync(FULLM, v0, off);
        float t1 = __shfl_down_sync(FULLM, v1, off);
        float t2 = __shfl_down_sync(FULLM, v2, off);
        float t3 = __shfl_down_sync(FULLM, v3, off);
        if (p[i]) { v0 += t0; v1 += t1; v2 += t2; v3 += t3; }
    }
    if (head) red4(addr, v0, v1, v2, v3);
}

// pair emit: direct red4 of prefix on split, segred of combined keyed r1
#define PAIR_EMIT(valA, valB, addr0, addr1)                                    \
    do {                                                                       \
        if (split) red4(addr0, (valA)[0], (valA)[1], (valA)[2], (valA)[3]);    \
        float c0 = split ? (valB)[0] : (valA)[0] + (valB)[0];                  \
        float c1 = split ? (valB)[1] : (valA)[1] + (valB)[1];                  \
        float c2 = split ? (valB)[2] : (valA)[2] + (valB)[2];                  \
        float c3 = split ? (valB)[3] : (valA)[3] + (valB)[3];                  \
        segred4(c0, c1, c2, c3, p, head, addr1);                               \
    } while (0)

// quad emit: prefix runs red4'd directly, tail run segred'd keyed on r3
__device__ __forceinline__ void quad_emit4(
    const float* vA, const float* vB, const float* vC, const float* vD,
    bool sp0, bool sp1, bool sp2, const int r[4],
    const bool p[5], bool head, float* base, int stride, int off)
{
    float a = vA[0], b = vA[1], c = vA[2], d = vA[3];
    if (sp0) { red4(base + (size_t)r[0]*stride + off, a, b, c, d);
               a = vB[0]; b = vB[1]; c = vB[2]; d = vB[3]; }
    else     { a += vB[0]; b += vB[1]; c += vB[2]; d += vB[3]; }
    if (sp1) { red4(base + (size_t)r[1]*stride + off, a, b, c, d);
               a = vC[0]; b = vC[1]; c = vC[2]; d = vC[3]; }
    else     { a += vC[0]; b += vC[1]; c += vC[2]; d += vC[3]; }
    if (sp2) { red4(base + (size_t)r[2]*stride + off, a, b, c, d);
               a = vD[0]; b = vD[1]; c = vD[2]; d = vD[3]; }
    else     { a += vD[0]; b += vD[1]; c += vD[2]; d += vD[3]; }
    segred4(a, b, c, d, p, head, base + (size_t)r[3]*stride + off);
}

#define SEG_SETUP_R(rkey)                                                      \
    int lane = threadIdx.x & 31;                                               \
    uint32_t seg = __match_any_sync(FULLM, rkey);                              \
    bool head = (lane == (__ffs(seg) - 1));                                    \
    bool p[5];                                                                 \
    {                                                                          \
        _Pragma("unroll")                                                      \
        for (int i = 0, off = 1; i < 5; i++, off <<= 1) {                      \
            int ln = lane + off;                                               \
            p[i] = (ln < 32) && ((seg >> ln) & 1u);                            \
        }                                                                      \
    }

// quad prologue: indices, geometry, split flags, bins
#define QUAD_PROLOGUE()                                                        \
    int Q = blockIdx.x * 256 + threadIdx.x;                                    \
    int4 rr = ((const int4*)g_rs)[Q];                                          \
    int r[4] = {rr.x, rr.y, rr.z, rr.w};                                       \
    int s[4]; float dist[4], ux[4], uy[4], uz[4];                              \
    {                                                                          \
        _Pragma("unroll")                                                      \
        for (int i = 0; i < 4; i++) {                                          \
            float4 rec = g_rec[4*Q + i];                                       \
            unpack_rec(rec, s[i], dist[i], ux[i], uy[i], uz[i]);               \
        }                                                                      \
    }                                                                          \
    bool sp0 = (r[0] != r[1]), sp1 = (r[1] != r[2]), sp2 = (r[2] != r[3]);     \
    SEG_SETUP_R(r[3]);                                                         \
    int bin[4]; float fr[4];                                                   \
    {                                                                          \
        _Pragma("unroll")                                                      \
        for (int i = 0; i < 4; i++) bin_of(dist[i], bin[i], fr[i]);            \
    }

// ---------------- init -------------------------------------------------------
__global__ void k_init() {
    long i0 = (long)blockIdx.x * blockDim.x + threadIdx.x;
    long stride = (long)gridDim.x * blockDim.x;
    for (long i = i0; i < N_NODES / 4; i += stride)
        ((int4*)g_cnt)[i] = make_int4(0, 0, 0, 0);
    float4 z = make_float4(0.f, 0.f, 0.f, 0.f);
    for (long i = i0; i < N_NODES;     i += stride) ((float4*)g_a0)[i] = z;
    for (long i = i0; i < N_NODES * 3; i += stride) ((float4*)g_a1)[i] = z;
    for (long i = i0; i < N_NODES * 2; i += stride) ((float4*)g_b0)[i] = z;
    for (long i = i0; i < N_NODES * 9; i += stride) ((float4*)g_b1)[i] = z;
    for (long i = i0; i < N_NODES * 2; i += stride) ((float4*)g_c0)[i] = z;
}

// ---------------- radial table build -----------------------------------------
__global__ void k_table(const float* __restrict__ rw1, const float* __restrict__ rb1,
                        const float* __restrict__ rw2, const float* __restrict__ rb2) {
    int bin = blockIdx.x * blockDim.x + threadIdx.x;
    if (bin >= NBINS) return;
    float d = (float)bin * (1.0f / INV_DELTA);
    float rbf[8];
#pragma unroll
    for (int b = 0; b < 8; b++) {
        float t = d - 0.5f * (float)b;
        rbf[b] = __expf(-4.0f * t * t);
    }
    float R[4];
    radial_exact(0, rbf, R, rw1, rb1, rw2, rb2);
#pragma unroll
    for (int c = 0; c < 4; c++) g_tab1[bin*8 + c] = R[c];
    radial_exact(1, rbf, R, rw1, rb1, rw2, rb2);
#pragma unroll
    for (int c = 0; c < 4; c++) g_tab1[bin*8 + 4 + c] = R[c];
#pragma unroll
    for (int pth = 2; pth <= 6; pth++) {
        radial_exact(pth, rbf, R, rw1, rb1, rw2, rb2);
#pragma unroll
        for (int c = 0; c < 4; c++) g_tab2[bin*20 + (pth-2)*4 + c] = R[c];
    }
    radial_exact(7, rbf, R, rw1, rb1, rw2, rb2);
#pragma unroll
    for (int c = 0; c < 4; c++) g_tab3[bin*8 + c] = R[c];
    radial_exact(8, rbf, R, rw1, rb1, rw2, rb2);
#pragma unroll
    for (int c = 0; c < 4; c++) g_tab3[bin*8 + 4 + c] = R[c];
}

// ---------------- CSR build --------------------------------------------------
__global__ void k_hist(const int* __restrict__ rcv) {
    int e = blockIdx.x * blockDim.x + threadIdx.x;
    if (e < N_EDGES) atomicAdd(&g_cnt[rcv[e]], 1);
}

__global__ void k_scanA() {
    __shared__ int sd[256];
    int b = blockIdx.x, t = threadIdx.x;
    int i = b * 512 + t * 2;
    int e0 = g_cnt[i], e1 = g_cnt[i + 1];
    int s = e0 + e1;
    sd[t] = s;
    __syncthreads();
#pragma unroll
    for (int off = 1; off < 256; off <<= 1) {
        int v = (t >= off) ? sd[t - off] : 0;
        __syncthreads();
        sd[t] += v;
        __syncthreads();
    }
    int incl = sd[t];
    int excl = incl - s;
    g_off[i]     = excl;
    g_off[i + 1] = excl + e0;
    if (t == 255) g_bs[b] = incl;
}

__global__ void k_scanB() {
    __shared__ int sd[256];
    int t = threadIdx.x;
    int v = g_bs[t];
    sd[t] = v;
    __syncthreads();
#pragma unroll
    for (int off = 1; off < 256; off <<= 1) {
        int x = (t >= off) ? sd[t - off] : 0;
        __syncthreads();
        sd[t] += x;
        __syncthreads();
    }
    g_bs[t] = sd[t] - v;   // exclusive
}

__global__ void k_scanC() {
    int b = blockIdx.x, t = threadIdx.x;
    int add = g_bs[b];
    int i = b * 512 + t * 2;
    int o0 = g_off[i] + add, o1 = g_off[i + 1] + add;
    g_off[i] = o0;  g_off[i + 1] = o1;
    g_cur[i] = o0;  g_cur[i + 1] = o1;
    if (b == 0 && t == 0) g_off[N_NODES] = N_EDGES;
}

__global__ void k_fill() {
    __shared__ int offs[257];
    int base = blockIdx.x * 256;
    if (threadIdx.x < 256) offs[threadIdx.x] = g_off[base + threadIdx.x];
    if (threadIdx.x == 0)  offs[256] = g_off[base + 256];
    __syncthreads();
    int beg = offs[0], end = offs[256];
    for (int idx = beg + threadIdx.x; idx < end; idx += 256) {
        int lo = 0, hi = 256;
#pragma unroll
        for (int it = 0; it < 8; it++) {
            int mid = (lo + hi) >> 1;
            if (offs[mid] <= idx) lo = mid; else hi = mid;
        }
        g_rs[idx] = base + lo;
    }
}

__global__ void k_scatter(const float* __restrict__ pos,
                          const int* __restrict__ snd, const int* __restrict__ rcv) {
    int e = blockIdx.x * blockDim.x + threadIdx.x;
    if (e >= N_EDGES) return;
    int s = snd[e], r = rcv[e];
    float sx = pos[3*s+0], sy = pos[3*s+1], sz = pos[3*s+2];
    float rx = pos[3*r+0], ry = pos[3*r+1], rz = pos[3*r+2];
    float dx = rx - sx, dy = ry - sy, dz = rz - sz;
    float dist = sqrtf(dx*dx + dy*dy + dz*dz);
    float inv = 1.0f / fmaxf(dist, 1e-9f);
    int slot = atomicAdd(&g_cur[r], 1);
    __half2 xy = __floats2half2_rn(dx * inv, dy * inv);
    __half2 zp = __floats2half2_rn(dz * inv, 0.f);
    float4 rec;
    rec.x = dist;
    rec.y = __int_as_float(s);
    rec.z = *reinterpret_cast<float*>(&xy);
    rec.w = *reinterpret_cast<float*>(&zp);
    g_rec[slot] = rec;
}

// ---------------- edge kernels -----------------------------------------------

// Layer 1 (QUAD): paths 0,1
__global__ void __launch_bounds__(256, 2)
k_edge1(const float* __restrict__ nf, const float* __restrict__ wsi1) {
    __shared__ __align__(16) float st[NBINS * 8];
    __shared__ float s1[4];
    for (int i = threadIdx.x; i < NBINS * 2; i += 256)
        ((float4*)st)[i] = ((const float4*)g_tab1)[i];
    if (threadIdx.x < 4) s1[threadIdx.x] = wsi1[threadIdx.x];
    __syncthreads();

    QUAD_PROLOGUE();

    float xs[4][4];
#pragma unroll
    for (int i = 0; i < 4; i++) {
        float nfv = __ldg(&nf[s[i]]);
#pragma unroll
        for (int c = 0; c < 4; c++) xs[i][c] = s1[c] * nfv;
    }

    // a0
    {
        float v[4][4];
#pragma unroll
        for (int i = 0; i < 4; i++) {
            float R[4];
            lerp4(st, 8, bin[i], fr[i], 0, R);
#pragma unroll
            for (int c = 0; c < 4; c++) v[i][c] = R[c] * xs[i][c];
        }
        quad_emit4(v[0], v[1], v[2], v[3], sp0, sp1, sp2, r, p, head, g_a0, 4, 0);
    }
    // a1 (3 groups)
    float t[4][4];
#pragma unroll
    for (int i = 0; i < 4; i++) {
        float R[4];
        lerp4(st, 8, bin[i], fr[i], 4, R);
#pragma unroll
        for (int c = 0; c < 4; c++) t[i][c] = R[c] * xs[i][c];
    }
    {
        float v[4][4];
#pragma unroll
        for (int i = 0; i < 4; i++) {
            v[i][0]=t[i][0]*ux[i]; v[i][1]=t[i][0]*uy[i];
            v[i][2]=t[i][0]*uz[i]; v[i][3]=t[i][1]*ux[i];
        }
        quad_emit4(v[0], v[1], v[2], v[3], sp0, sp1, sp2, r, p, head, g_a1, 12, 0);
#pragma unroll
        for (int i = 0; i < 4; i++) {
            v[i][0]=t[i][1]*uy[i]; v[i][1]=t[i][1]*uz[i];
            v[i][2]=t[i][2]*ux[i]; v[i][3]=t[i][2]*uy[i];
        }
        quad_emit4(v[0], v[1], v[2], v[3], sp0, sp1, sp2, r, p, head, g_a1, 12, 4);
#pragma unroll
        for (int i = 0; i < 4; i++) {
            v[i][0]=t[i][2]*uz[i]; v[i][1]=t[i][3]*ux[i];
            v[i][2]=t[i][3]*uy[i]; v[i][3]=t[i][3]*uz[i];
        }
        quad_emit4(v[0], v[1], v[2], v[3], sp0, sp1, sp2, r, p, head, g_a1, 12, 8);
    }
}

// node update 1: si2 + gate -> packed fp16
__global__ void k_node1(const float* __restrict__ w20, const float* __restrict__ w21) {
    int n = blockIdx.x * blockDim.x + threadIdx.x;
    if (n >= N_NODES) return;
    float4 a0 = ((const float4*)g_a0)[n];
    float in0[4] = {a0.x, a0.y, a0.z, a0.w};
    float outv[16];
#pragma unroll
    for (int o = 0; o < 4; o++) {
        float sacc = 0.f;
#pragma unroll
        for (int i = 0; i < 4; i++) sacc = fmaf(__ldg(&w20[o*4+i]), in0[i], sacc);
        outv[o] = sacc * sigmoidf(sacc);
    }
    float a1[12];
    float4 t0 = ((const float4*)g_a1)[n*3+0];
    float4 t1 = ((const float4*)g_a1)[n*3+1];
    float4 t2 = ((const float4*)g_a1)[n*3+2];
    a1[0]=t0.x; a1[1]=t0.y; a1[2]=t0.z; a1[3]=t0.w;
    a1[4]=t1.x; a1[5]=t1.y; a1[6]=t1.z; a1[7]=t1.w;
    a1[8]=t2.x; a1[9]=t2.y; a1[10]=t2.z; a1[11]=t2.w;
#pragma unroll
    for (int o = 0; o < 4; o++) {
        float vx = 0.f, vy = 0.f, vz = 0.f;
#pragma unroll
        for (int i = 0; i < 4; i++) {
            float w = __ldg(&w21[o*4+i]);
            vx = fmaf(w, a1[i*3+0], vx);
            vy = fmaf(w, a1[i*3+1], vy);
            vz = fmaf(w, a1[i*3+2], vz);
        }
        float nrm = sqrtf(vx*vx + vy*vy + vz*vz);
        float gt = sigmoidf(nrm);
        outv[4+o*3+0] = vx*gt; outv[4+o*3+1] = vy*gt; outv[4+o*3+2] = vz*gt;
    }
    store_packed16(g_xb, n, outv);
}

// Layer 2 (PAIR): paths 2..6
__global__ void k_edge2() {
    __shared__ __align__(16) float st[NBINS * 20];
    for (int i = threadIdx.x; i < NBINS * 5; i += 256)
        ((float4*)st)[i] = ((const float4*)g_tab2)[i];
    __syncthreads();

    int pbase = blockIdx.x * (PB_CHUNKS * 256) + threadIdx.x;
#pragma unroll 1
    for (int c = 0; c < PB_CHUNKS; c++) {
        int P = pbase + c * 256;
        int e0 = 2 * P, e1 = 2 * P + 1;
        int r0 = g_rs[e0], r1 = g_rs[e1];
        float4 recA = g_rec[e0], recB = g_rec[e1];
        int sA, sB; float dA, uxA, uyA, uzA, dB, uxB, uyB, uzB;
        unpack_rec(recA, sA, dA, uxA, uyA, uzA);
        unpack_rec(recB, sB, dB, uxB, uyB, uzB);
        bool split = (r0 != r1);
        SEG_SETUP_R(r1);
        int binA, binB; float frA, frB;
        bin_of(dA, binA, frA);
        bin_of(dB, binB, frB);

        float vA[16], vB[16];
        load_packed16(g_xb, sA, vA);
        load_packed16(g_xb, sB, vB);
        float* xsA = vA; float* x1A = vA + 4;
        float* xsB = vB; float* x1B = vB + 4;

        float RA[4], RB[4];
        // p00_0 -> b0[0:4]
        lerp4(st, 20, binA, frA, 0, RA);
        lerp4(st, 20, binB, frB, 0, RB);
        {
            float wA[4], wB[4];
#pragma unroll
            for (int cc = 0; cc < 4; cc++) { wA[cc]=RA[cc]*xsA[cc]; wB[cc]=RB[cc]*xsB[cc]; }
            PAIR_EMIT(wA, wB, &g_b0[r0*8], &g_b0[r1*8]);
        }
        // p11_0 -> b0[4:8]
        lerp4(st, 20, binA, frA, 12, RA);
        lerp4(st, 20, binB, frB, 12, RB);
        {
            float wA[4], wB[4];
            wA[0] = RA[0]*INV_SQRT3*(x1A[0]*uxA + x1A[1]*uyA + x1A[2]*uzA);
            wA[1] = RA[1]*INV_SQRT3*(x1A[3]*uxA + x1A[4]*uyA + x1A[5]*uzA);
            wA[2] = RA[2]*INV_SQRT3*(x1A[6]*uxA + x1A[7]*uyA + x1A[8]*uzA);
            wA[3] = RA[3]*INV_SQRT3*(x1A[9]*uxA + x1A[10]*uyA + x1A[11]*uzA);
            wB[0] = RB[0]*INV_SQRT3*(x1B[0]*uxB + x1B[1]*uyB + x1B[2]*uzB);
            wB[1] = RB[1]*INV_SQRT3*(x1B[3]*uxB + x1B[4]*uyB + x1B[5]*uzB);
            wB[2] = RB[2]*INV_SQRT3*(x1B[6]*uxB + x1B[7]*uyB + x1B[8]*uzB);
            wB[3] = RB[3]*INV_SQRT3*(x1B[9]*uxB + x1B[10]*uyB + x1B[11]*uzB);
            PAIR_EMIT(wA, wB, &g_b0[r0*8+4], &g_b0[r1*8+4]);
        }
        float* b1A = &g_b1[r0*36];
        float* b1B = &g_b1[r1*36];
        // p01_1
        lerp4(st, 20, binA, frA, 4, RA);
        lerp4(st, 20, binB, frB, 4, RB);
        {
            float mA[12], mB[12];
#pragma unroll
            for (int cc = 0; cc < 4; cc++) {
                float tA = RA[cc]*xsA[cc], tB = RB[cc]*xsB[cc];
                mA[cc*3+0]=tA*uxA; mA[cc*3+1]=tA*uyA; mA[cc*3+2]=tA*uzA;
                mB[cc*3+0]=tB*uxB; mB[cc*3+1]=tB*uyB; mB[cc*3+2]=tB*uzB;
            }
            PAIR_EMIT(mA+0, mB+0, b1A+0, b1B+0);
            PAIR_EMIT(mA+4, mB+4, b1A+4, b1B+4);
            PAIR_EMIT(mA+8, mB+8, b1A+8, b1B+8);
        }
        // p10_1
        lerp4(st, 20, binA, frA, 8, RA);
        lerp4(st, 20, binB, frB, 8, RB);
        {
            float mA[12], mB[12];
#pragma unroll
            for (int cc = 0; cc < 4; cc++) {
                mA[cc*3+0]=RA[cc]*x1A[cc*3+0]; mA[cc*3+1]=RA[cc]*x1A[cc*3+1]; mA[cc*3+2]=RA[cc]*x1A[cc*3+2];
                mB[cc*3+0]=RB[cc]*x1B[cc*3+0]; mB[cc*3+1]=RB[cc]*x1B[cc*3+1]; mB[cc*3+2]=RB[cc]*x1B[cc*3+2];
            }
            PAIR_EMIT(mA+0, mB+0, b1A+12, b1B+12);
            PAIR_EMIT(mA+4, mB+4, b1A+16, b1B+16);
            PAIR_EMIT(mA+8, mB+8, b1A+20, b1B+20);
        }
        // p11_1
        lerp4(st, 20, binA, frA, 16, RA);
        lerp4(st, 20, binB, frB, 16, RB);
        {
            float mA[12], mB[12];
#pragma unroll
            for (int cc = 0; cc < 4; cc++) {
                float ax = x1A[cc*3+0], ay = x1A[cc*3+1], az = x1A[cc*3+2];
                float tA = RA[cc] * INV_SQRT2;
                mA[cc*3+0]=tA*(ay*uzA - az*uyA);
                mA[cc*3+1]=tA*(az*uxA - ax*uzA);
                mA[cc*3+2]=tA*(ax*uyA - ay*uxA);
                float bx = x1B[cc*3+0], by = x1B[cc*3+1], bz = x1B[cc*3+2];
                float tB = RB[cc] * INV_SQRT2;
                mB[cc*3+0]=tB*(by*uzB - bz*uyB);
                mB[cc*3+1]=tB*(bz*uxB - bx*uzB);
                mB[cc*3+2]=tB*(bx*uyB - by*uxB);
            }
            PAIR_EMIT(mA+0, mB+0, b1A+24, b1B+24);
            PAIR_EMIT(mA+4, mB+4, b1A+28, b1B+28);
            PAIR_EMIT(mA+8, mB+8, b1A+32, b1B+32);
        }
    }
}

// node update 2: si3 + gate -> packed fp16
__global__ void k_node2(const float* __restrict__ w30, const float* __restrict__ w31) {
    int n = blockIdx.x * blockDim.x + threadIdx.x;
    if (n >= N_NODES) return;
    float b0[8];
    {
        float4 t0 = ((const float4*)g_b0)[n*2+0];
        float4 t1 = ((const float4*)g_b0)[n*2+1];
        b0[0]=t0.x; b0[1]=t0.y; b0[2]=t0.z; b0[3]=t0.w;
        b0[4]=t1.x; b0[5]=t1.y; b0[6]=t1.z; b0[7]=t1.w;
    }
    float outv[16];
#pragma unroll
    for (int o = 0; o < 4; o++) {
        float sacc = 0.f;
#pragma unroll
        for (int i = 0; i < 8; i++) sacc = fmaf(__ldg(&w30[o*8+i]), b0[i], sacc);
        outv[o] = sacc * sigmoidf(sacc);
    }
    float b1[36];
#pragma unroll
    for (int q = 0; q < 9; q++) {
        float4 t = ((const float4*)g_b1)[n*9+q];
        b1[q*4+0]=t.x; b1[q*4+1]=t.y; b1[q*4+2]=t.z; b1[q*4+3]=t.w;
    }
#pragma unroll
    for (int o = 0; o < 4; o++) {
        float vx = 0.f, vy = 0.f, vz = 0.f;
#pragma unroll
        for (int i = 0; i < 12; i++) {
            float w = __ldg(&w31[o*12+i]);
            vx = fmaf(w, b1[i*3+0], vx);
            vy = fmaf(w, b1[i*3+1], vy);
            vz = fmaf(w, b1[i*3+2], vz);
        }
        float nrm = sqrtf(vx*vx + vy*vy + vz*vz);
        float gt = sigmoidf(nrm);
        outv[4+o*3+0]=vx*gt; outv[4+o*3+1]=vy*gt; outv[4+o*3+2]=vz*gt;
    }
    store_packed16(g_xc, n, outv);
}

// Layer 3 (QUAD): paths 7,8
__global__ void __launch_bounds__(256, 2)
k_edge3() {
    __shared__ __align__(16) float st[NBINS * 8];
    for (int i = threadIdx.x; i < NBINS * 2; i += 256)
        ((float4*)st)[i] = ((const float4*)g_tab3)[i];
    __syncthreads();

    QUAD_PROLOGUE();

    uint4 pk0[4], pk1[4];
#pragma unroll
    for (int i = 0; i < 4; i++) {
        pk0[i] = ((const uint4*)g_xc)[2*s[i]+0];
        pk1[i] = ((const uint4*)g_xc)[2*s[i]+1];
    }

    // c0[0:4] : R7 * x0
    {
        float v[4][4];
#pragma unroll
        for (int i = 0; i < 4; i++) {
            float xs[4];
            unpack4(make_uint2(pk0[i].x, pk0[i].y), xs);
            float R[4];
            lerp4(st, 8, bin[i], fr[i], 0, R);
#pragma unroll
            for (int c = 0; c < 4; c++) v[i][c] = R[c] * xs[c];
        }
        quad_emit4(v[0], v[1], v[2], v[3], sp0, sp1, sp2, r, p, head, g_c0, 8, 0);
    }
    // c0[4:8] : R8 * (x1 . u)/sqrt3
    {
        float v[4][4];
#pragma unroll
        for (int i = 0; i < 4; i++) {
            float a[4], b[4], c4[4];
            unpack4(make_uint2(pk0[i].z, pk0[i].w), a);
            unpack4(make_uint2(pk1[i].x, pk1[i].y), b);
            unpack4(make_uint2(pk1[i].z, pk1[i].w), c4);
            float x1l[12] = {a[0],a[1],a[2],a[3], b[0],b[1],b[2],b[3],
                             c4[0],c4[1],c4[2],c4[3]};
            float R[4];
            lerp4(st, 8, bin[i], fr[i], 4, R);
#pragma unroll
            for (int c = 0; c < 4; c++) {
                float dt = x1l[c*3+0]*ux[i] + x1l[c*3+1]*uy[i] + x1l[c*3+2]*uz[i];
                v[i][c] = R[c] * INV_SQRT3 * dt;
            }
        }
        quad_emit4(v[0], v[1], v[2], v[3], sp0, sp1, sp2, r, p, head, g_c0, 8, 4);
    }
}

// readout
__global__ void k_final(const float* __restrict__ w4, const float* __restrict__ wout,
                        float* __restrict__ out) {
    int gw = (blockIdx.x * blockDim.x + threadIdx.x) >> 5;
    int lane = threadIdx.x & 31;
    if (gw >= N_GRAPH) return;
    int n = gw * NPG + lane;
    float c0[8];
    {
        float4 t0 = ((const float4*)g_c0)[n*2+0];
        float4 t1 = ((const float4*)g_c0)[n*2+1];
        c0[0]=t0.x; c0[1]=t0.y; c0[2]=t0.z; c0[3]=t0.w;
        c0[4]=t1.x; c0[5]=t1.y; c0[6]=t1.z; c0[7]=t1.w;
    }
    float f[4];
#pragma unroll
    for (int o = 0; o < 4; o++) {
        float sacc = 0.f;
#pragma unroll
        for (int i = 0; i < 8; i++) sacc = fmaf(__ldg(&w4[o*8+i]), c0[i], sacc);
        f[o] = sacc * sigmoidf(sacc);
    }
#pragma unroll
    for (int o = 0; o < 4; o++) {
#pragma unroll
        for (int off = 16; off > 0; off >>= 1)
            f[o] += __shfl_xor_sync(FULLM, f[o], off);
    }
    if (lane < 8) {
        float acc = 0.f;
#pragma unroll
        for (int o = 0; o < 4; o++) acc = fmaf(__ldg(&wout[lane*4+o]), f[o], acc);
        out[gw*8 + lane] = acc;
    }
}

// ---------------- launch ----------------------------------------------------
extern "C" void kernel_launch(void* const* d_in, const int* in_sizes, int n_in,
                              void* d_out, int out_size) {
    const float* pos   = (const float*)d_in[0];
    const float* nf    = (const float*)d_in[1];
    const float* w_si1 = (const float*)d_in[2];
    const float* w20   = (const float*)d_in[3];
    const float* w21   = (const float*)d_in[4];
    const float* w30   = (const float*)d_in[5];
    const float* w31   = (const float*)d_in[6];
    const float* w4    = (const float*)d_in[7];
    const float* wout  = (const float*)d_in[8];
    const float* rw1   = (const float*)d_in[9];
    const float* rb1   = (const float*)d_in[10];
    const float* rw2   = (const float*)d_in[11];
    const float* rb2   = (const float*)d_in[12];
    const int*   snd   = (const int*)d_in[13];
    const int*   rcv   = (const int*)d_in[14];
    float* out = (float*)d_out;

    const int TB = 256;
    k_init   <<<2048, TB>>>();
    k_table  <<<2, TB>>>(rw1, rb1, rw2, rb2);
    k_hist   <<<N_EDGES/TB, TB>>>(rcv);
    k_scanA  <<<256, 256>>>();
    k_scanB  <<<1, 256>>>();
    k_scanC  <<<256, 256>>>();
    k_fill   <<<N_NODES/256, 256>>>();
    k_scatter<<<N_EDGES/TB, TB>>>(pos, snd, rcv);
    k_edge1  <<<QB_BLOCKS, TB>>>(nf, w_si1);
    k_node1  <<<N_NODES/TB, TB>>>(w20, w21);
    k_edge2  <<<PB_BLOCKS, TB>>>();
    k_node2  <<<N_NODES/TB, TB>>>(w30, w31);
    k_edge3  <<<QB_BLOCKS, TB>>>();
    k_final  <<<(N_GRAPH * 32)/TB, TB>>>(w4, wout, out);
}

// round 16
// speedup vs baseline: 1.0224x; 1.0224x over previous
#include <cuda_runtime.h>
#include <cuda_fp16.h>
#include <cstdint>

#define N_GRAPH   4096
#define NPG       32
#define N_NODES   (N_GRAPH * NPG)      // 131072
#define N_EDGES   (N_NODES * 16)       // 2097152
#define N_PAIRS   (N_EDGES / 2)        // 1048576
#define INV_SQRT3 0.57735026918962576451f
#define INV_SQRT2 0.70710678118654752440f
#define FULLM     0xFFFFFFFFu

#define NBINS     512
#define INV_DELTA 100.0f               // Δ = 0.01, domain [0, 5.11]

#define PB_BLOCKS 2048                 // pairs: 2048 x 2 chunks x 256
#define PB_CHUNKS 2

// ---------------- scratch (static device arrays) -----------------------------
__device__ int   g_cnt[N_NODES];
__device__ int   g_off[N_NODES + 1];
__device__ int   g_cur[N_NODES];
__device__ int   g_bs [256];
__device__ __align__(16) int g_rs [N_EDGES];      // receiver per sorted slot
__device__ __align__(16) float4 g_rec[N_EDGES];   // {dist, s_bits, h2(ux,uy), h2(uz,0)}
__device__ __align__(16) float4 g_pos4[N_NODES];  // padded positions

// radial tables
__device__ __align__(16) float g_tab1[NBINS * 8];   // R0[4] R1[4]
__device__ __align__(16) float g_tab2[NBINS * 20];  // R2..R6
__device__ __align__(16) float g_tab3[NBINS * 8];   // R7[4] R8[4]

__device__ __align__(16) float g_a0 [N_NODES * 4];
__device__ __align__(16) float g_a1 [N_NODES * 12];
__device__ __align__(16) __half g_xb[N_NODES * 16];
__device__ __align__(16) float g_b0 [N_NODES * 8];
__device__ __align__(16) float g_b1 [N_NODES * 36];
__device__ __align__(16) __half g_xc[N_NODES * 16];
__device__ __align__(16) float g_c0 [N_NODES * 8];

// ---------------- helpers ---------------------------------------------------
__device__ __forceinline__ void red4(float* p, float a, float b, float c, float d) {
    asm volatile("red.global.add.v4.f32 [%0], {%1,%2,%3,%4};"
                 :: "l"(p), "f"(a), "f"(b), "f"(c), "f"(d) : "memory");
}

__device__ __forceinline__ float sigmoidf(float x) {
    return 1.0f / (1.0f + __expf(-x));
}

__device__ __forceinline__ void unpack_rec(float4 rec, int& s, float& dist,
                                           float& ux, float& uy, float& uz) {
    dist = rec.x;
    s = __float_as_int(rec.y);
    __half2 xy = *reinterpret_cast<__half2*>(&rec.z);
    __half2 zp = *reinterpret_cast<__half2*>(&rec.w);
    float2 f = __half22float2(xy);
    ux = f.x; uy = f.y;
    uz = __half2float(__low2half(zp));
}

// exact radial (k_table only)
__device__ void radial_exact(int p, const float rbf[8], float R[4],
                             const float* w1g, const float* b1g,
                             const float* w2g, const float* b2g) {
    float h[8];
#pragma unroll
    for (int j = 0; j < 8; j++) h[j] = b1g[p*8 + j];
#pragma unroll
    for (int b = 0; b < 8; b++) {
        float rb = rbf[b];
#pragma unroll
        for (int j = 0; j < 8; j++) h[j] = fmaf(rb, w1g[p*64 + b*8 + j], h[j]);
    }
#pragma unroll
    for (int j = 0; j < 8; j++) h[j] = fmaxf(h[j], 0.0f);
#pragma unroll
    for (int c = 0; c < 4; c++) R[c] = b2g[p*4 + c];
#pragma unroll
    for (int j = 0; j < 8; j++) {
        float hj = h[j];
#pragma unroll
        for (int c = 0; c < 4; c++) R[c] = fmaf(hj, w2g[p*32 + j*4 + c], R[c]);
    }
}

__device__ __forceinline__ void lerp4(const float* st, int stride, int bin,
                                      float frac, int off, float R[4]) {
    float4 a = *reinterpret_cast<const float4*>(st + bin * stride + off);
    float4 b = *reinterpret_cast<const float4*>(st + (bin + 1) * stride + off);
    R[0] = fmaf(frac, b.x - a.x, a.x);
    R[1] = fmaf(frac, b.y - a.y, a.y);
    R[2] = fmaf(frac, b.z - a.z, a.z);
    R[3] = fmaf(frac, b.w - a.w, a.w);
}

__device__ __forceinline__ void bin_of(float dist, int& bin, float& frac) {
    float binf = dist * INV_DELTA;
    bin = min((int)binf, NBINS - 2);
    frac = fminf(binf - (float)bin, 1.0f);
}

__device__ __forceinline__ void store_packed16(__half* base, int n, const float* v) {
    uint4 pk[2];
    __half2* hp = reinterpret_cast<__half2*>(pk);
#pragma unroll
    for (int i = 0; i < 8; i++) hp[i] = __floats2half2_rn(v[2*i], v[2*i+1]);
    reinterpret_cast<uint4*>(base)[2*n+0] = pk[0];
    reinterpret_cast<uint4*>(base)[2*n+1] = pk[1];
}

__device__ __forceinline__ void load_packed16(const __half* base, int n, float* v) {
    uint4 pk[2];
    pk[0] = reinterpret_cast<const uint4*>(base)[2*n+0];
    pk[1] = reinterpret_cast<const uint4*>(base)[2*n+1];
    const __half2* hp = reinterpret_cast<const __half2*>(pk);
#pragma unroll
    for (int i = 0; i < 8; i++) {
        float2 f = __half22float2(hp[i]);
        v[2*i] = f.x; v[2*i+1] = f.y;
    }
}

// segmented warp sum keyed by tail receiver
__device__ __forceinline__ void segred4(float v0, float v1, float v2, float v3,
                                        const bool p[5], bool head, float* addr) {
#pragma unroll
    for (int i = 0, off = 1; i < 5; i++, off <<= 1) {
        float t0 = __shfl_down_sync(FULLM, v0, off);
        float t1 = __shfl_down_sync(FULLM, v1, off);
        float t2 = __shfl_down_sync(FULLM, v2, off);
        float t3 = __shfl_down_sync(FULLM, v3, off);
        if (p[i]) { v0 += t0; v1 += t1; v2 += t2; v3 += t3; }
    }
    if (head) red4(addr, v0, v1, v2, v3);
}

// pair emit: direct red4 of prefix on split, segred of combined keyed r1
#define PAIR_EMIT(valA, valB, addr0, addr1)                                    \
    do {                                                                       \
        if (split) red4(addr0, (valA)[0], (valA)[1], (valA)[2], (valA)[3]);    \
        float c0 = split ? (valB)[0] : (valA)[0] + (valB)[0];                  \
        float c1 = split ? (valB)[1] : (valA)[1] + (valB)[1];                  \
        float c2 = split ? (valB)[2] : (valA)[2] + (valB)[2];                  \
        float c3 = split ? (valB)[3] : (valA)[3] + (valB)[3];                  \
        segred4(c0, c1, c2, c3, p, head, addr1);                               \
    } while (0)

#define SEG_SETUP_R(rkey)                                                      \
    int lane = threadIdx.x & 31;                                               \
    uint32_t seg = __match_any_sync(FULLM, rkey);                              \
    bool head = (lane == (__ffs(seg) - 1));                                    \
    bool p[5];                                                                 \
    {                                                                          \
        _Pragma("unroll")                                                      \
        for (int i = 0, off = 1; i < 5; i++, off <<= 1) {                      \
            int ln = lane + off;                                               \
            p[i] = (ln < 32) && ((seg >> ln) & 1u);                            \
        }                                                                      \
    }

// ---------------- init -------------------------------------------------------
__global__ void k_init() {
    long i0 = (long)blockIdx.x * blockDim.x + threadIdx.x;
    long stride = (long)gridDim.x * blockDim.x;
    for (long i = i0; i < N_NODES / 4; i += stride)
        ((int4*)g_cnt)[i] = make_int4(0, 0, 0, 0);
    float4 z = make_float4(0.f, 0.f, 0.f, 0.f);
    for (long i = i0; i < N_NODES;     i += stride) ((float4*)g_a0)[i] = z;
    for (long i = i0; i < N_NODES * 3; i += stride) ((float4*)g_a1)[i] = z;
    for (long i = i0; i < N_NODES * 2; i += stride) ((float4*)g_b0)[i] = z;
    for (long i = i0; i < N_NODES * 9; i += stride) ((float4*)g_b1)[i] = z;
    for (long i = i0; i < N_NODES * 2; i += stride) ((float4*)g_c0)[i] = z;
}

// pad positions into float4 (coalesced)
__global__ void k_pos4(const float* __restrict__ pos) {
    int n = blockIdx.x * blockDim.x + threadIdx.x;
    if (n >= N_NODES) return;
    g_pos4[n] = make_float4(pos[3*n+0], pos[3*n+1], pos[3*n+2], 0.f);
}

// ---------------- radial table build -----------------------------------------
__global__ void k_table(const float* __restrict__ rw1, const float* __restrict__ rb1,
                        const float* __restrict__ rw2, const float* __restrict__ rb2) {
    int bin = blockIdx.x * blockDim.x + threadIdx.x;
    if (bin >= NBINS) return;
    float d = (float)bin * (1.0f / INV_DELTA);
    float rbf[8];
#pragma unroll
    for (int b = 0; b < 8; b++) {
        float t = d - 0.5f * (float)b;
        rbf[b] = __expf(-4.0f * t * t);
    }
    float R[4];
    radial_exact(0, rbf, R, rw1, rb1, rw2, rb2);
#pragma unroll
    for (int c = 0; c < 4; c++) g_tab1[bin*8 + c] = R[c];
    radial_exact(1, rbf, R, rw1, rb1, rw2, rb2);
#pragma unroll
    for (int c = 0; c < 4; c++) g_tab1[bin*8 + 4 + c] = R[c];
#pragma unroll
    for (int pth = 2; pth <= 6; pth++) {
        radial_exact(pth, rbf, R, rw1, rb1, rw2, rb2);
#pragma unroll
        for (int c = 0; c < 4; c++) g_tab2[bin*20 + (pth-2)*4 + c] = R[c];
    }
    radial_exact(7, rbf, R, rw1, rb1, rw2, rb2);
#pragma unroll
    for (int c = 0; c < 4; c++) g_tab3[bin*8 + c] = R[c];
    radial_exact(8, rbf, R, rw1, rb1, rw2, rb2);
#pragma unroll
    for (int c = 0; c < 4; c++) g_tab3[bin*8 + 4 + c] = R[c];
}

// ---------------- CSR build --------------------------------------------------
__global__ void k_hist(const int* __restrict__ rcv) {
    int i = blockIdx.x * blockDim.x + threadIdx.x;   // N_EDGES/4 threads
    if (i >= N_EDGES / 4) return;
    int4 rr = ((const int4*)rcv)[i];
    atomicAdd(&g_cnt[rr.x], 1);
    atomicAdd(&g_cnt[rr.y], 1);
    atomicAdd(&g_cnt[rr.z], 1);
    atomicAdd(&g_cnt[rr.w], 1);
}

__global__ void k_scanA() {
    __shared__ int sd[256];
    int b = blockIdx.x, t = threadIdx.x;
    int i = b * 512 + t * 2;
    int e0 = g_cnt[i], e1 = g_cnt[i + 1];
    int s = e0 + e1;
    sd[t] = s;
    __syncthreads();
#pragma unroll
    for (int off = 1; off < 256; off <<= 1) {
        int v = (t >= off) ? sd[t - off] : 0;
        __syncthreads();
        sd[t] += v;
        __syncthreads();
    }
    int incl = sd[t];
    int excl = incl - s;
    g_off[i]     = excl;
    g_off[i + 1] = excl + e0;
    if (t == 255) g_bs[b] = incl;
}

__global__ void k_scanB() {
    __shared__ int sd[256];
    int t = threadIdx.x;
    int v = g_bs[t];
    sd[t] = v;
    __syncthreads();
#pragma unroll
    for (int off = 1; off < 256; off <<= 1) {
        int x = (t >= off) ? sd[t - off] : 0;
        __syncthreads();
        sd[t] += x;
        __syncthreads();
    }
    g_bs[t] = sd[t] - v;   // exclusive
}

__global__ void k_scanC() {
    int b = blockIdx.x, t = threadIdx.x;
    int add = g_bs[b];
    int i = b * 512 + t * 2;
    int o0 = g_off[i] + add, o1 = g_off[i + 1] + add;
    g_off[i] = o0;  g_off[i + 1] = o1;
    g_cur[i] = o0;  g_cur[i + 1] = o1;
    if (b == 0 && t == 0) g_off[N_NODES] = N_EDGES;
}

__global__ void k_fill() {
    __shared__ int offs[257];
    int base = blockIdx.x * 256;
    if (threadIdx.x < 256) offs[threadIdx.x] = g_off[base + threadIdx.x];
    if (threadIdx.x == 0)  offs[256] = g_off[base + 256];
    __syncthreads();
    int beg = offs[0], end = offs[256];
    for (int idx = beg + threadIdx.x; idx < end; idx += 256) {
        int lo = 0, hi = 256;
#pragma unroll
        for (int it = 0; it < 8; it++) {
            int mid = (lo + hi) >> 1;
            if (offs[mid] <= idx) lo = mid; else hi = mid;
        }
        g_rs[idx] = base + lo;
    }
}

__global__ void k_scatter(const int* __restrict__ snd, const int* __restrict__ rcv) {
    int e = blockIdx.x * blockDim.x + threadIdx.x;
    if (e >= N_EDGES) return;
    int s = snd[e], r = rcv[e];
    float4 ps = g_pos4[s];
    float4 pr = g_pos4[r];
    float dx = pr.x - ps.x, dy = pr.y - ps.y, dz = pr.z - ps.z;
    float dist = sqrtf(dx*dx + dy*dy + dz*dz);
    float inv = 1.0f / fmaxf(dist, 1e-9f);
    int slot = atomicAdd(&g_cur[r], 1);
    __half2 xy = __floats2half2_rn(dx * inv, dy * inv);
    __half2 zp = __floats2half2_rn(dz * inv, 0.f);
    float4 rec;
    rec.x = dist;
    rec.y = __int_as_float(s);
    rec.z = *reinterpret_cast<float*>(&xy);
    rec.w = *reinterpret_cast<float*>(&zp);
    g_rec[slot] = rec;
}

// ---------------- pair edge kernels ------------------------------------------

// Layer 1: paths 0,1
__global__ void k_edge1(const float* __restrict__ nf, const float* __restrict__ wsi1) {
    __shared__ __align__(16) float st[NBINS * 8];
    __shared__ float s1[4];
    for (int i = threadIdx.x; i < NBINS * 2; i += 256)
        ((float4*)st)[i] = ((const float4*)g_tab1)[i];
    if (threadIdx.x < 4) s1[threadIdx.x] = wsi1[threadIdx.x];
    __syncthreads();

    int pbase = blockIdx.x * (PB_CHUNKS * 256) + threadIdx.x;
#pragma unroll 1
    for (int c = 0; c < PB_CHUNKS; c++) {
        int P = pbase + c * 256;
        int e0 = 2 * P, e1 = 2 * P + 1;
        int r0 = g_rs[e0], r1 = g_rs[e1];
        float4 recA = g_rec[e0], recB = g_rec[e1];
        int sA, sB; float dA, uxA, uyA, uzA, dB, uxB, uyB, uzB;
        unpack_rec(recA, sA, dA, uxA, uyA, uzA);
        unpack_rec(recB, sB, dB, uxB, uyB, uzB);
        bool split = (r0 != r1);
        SEG_SETUP_R(r1);
        int binA, binB; float frA, frB;
        bin_of(dA, binA, frA);
        bin_of(dB, binB, frB);

        float R0A[4], R1A[4], R0B[4], R1B[4];
        lerp4(st, 8, binA, frA, 0, R0A);
        lerp4(st, 8, binA, frA, 4, R1A);
        lerp4(st, 8, binB, frB, 0, R0B);
        lerp4(st, 8, binB, frB, 4, R1B);
        float nfA = __ldg(&nf[sA]), nfB = __ldg(&nf[sB]);
        float xsA[4], xsB[4];
#pragma unroll
        for (int cc = 0; cc < 4; cc++) { xsA[cc] = s1[cc]*nfA; xsB[cc] = s1[cc]*nfB; }

        {
            float vA[4], vB[4];
#pragma unroll
            for (int cc = 0; cc < 4; cc++) { vA[cc]=R0A[cc]*xsA[cc]; vB[cc]=R0B[cc]*xsB[cc]; }
            PAIR_EMIT(vA, vB, &g_a0[r0*4], &g_a0[r1*4]);
        }
        float mA[12], mB[12];
#pragma unroll
        for (int cc = 0; cc < 4; cc++) {
            float tA = R1A[cc]*xsA[cc], tB = R1B[cc]*xsB[cc];
            mA[cc*3+0]=tA*uxA; mA[cc*3+1]=tA*uyA; mA[cc*3+2]=tA*uzA;
            mB[cc*3+0]=tB*uxB; mB[cc*3+1]=tB*uyB; mB[cc*3+2]=tB*uzB;
        }
        PAIR_EMIT(mA+0, mB+0, &g_a1[r0*12+0], &g_a1[r1*12+0]);
        PAIR_EMIT(mA+4, mB+4, &g_a1[r0*12+4], &g_a1[r1*12+4]);
        PAIR_EMIT(mA+8, mB+8, &g_a1[r0*12+8], &g_a1[r1*12+8]);
    }
}

// node update 1: si2 + gate -> packed fp16
__global__ void k_node1(const float* __restrict__ w20, const float* __restrict__ w21) {
    int n = blockIdx.x * blockDim.x + threadIdx.x;
    if (n >= N_NODES) return;
    float4 a0 = ((const float4*)g_a0)[n];
    float in0[4] = {a0.x, a0.y, a0.z, a0.w};
    float outv[16];
#pragma unroll
    for (int o = 0; o < 4; o++) {
        float sacc = 0.f;
#pragma unroll
        for (int i = 0; i < 4; i++) sacc = fmaf(__ldg(&w20[o*4+i]), in0[i], sacc);
        outv[o] = sacc * sigmoidf(sacc);
    }
    float a1[12];
    float4 t0 = ((const float4*)g_a1)[n*3+0];
    float4 t1 = ((const float4*)g_a1)[n*3+1];
    float4 t2 = ((const float4*)g_a1)[n*3+2];
    a1[0]=t0.x; a1[1]=t0.y; a1[2]=t0.z; a1[3]=t0.w;
    a1[4]=t1.x; a1[5]=t1.y; a1[6]=t1.z; a1[7]=t1.w;
    a1[8]=t2.x; a1[9]=t2.y; a1[10]=t2.z; a1[11]=t2.w;
#pragma unroll
    for (int o = 0; o < 4; o++) {
        float vx = 0.f, vy = 0.f, vz = 0.f;
#pragma unroll
        for (int i = 0; i < 4; i++) {
            float w = __ldg(&w21[o*4+i]);
            vx = fmaf(w, a1[i*3+0], vx);
            vy = fmaf(w, a1[i*3+1], vy);
            vz = fmaf(w, a1[i*3+2], vz);
        }
        float nrm = sqrtf(vx*vx + vy*vy + vz*vz);
        float gt = sigmoidf(nrm);
        outv[4+o*3+0] = vx*gt; outv[4+o*3+1] = vy*gt; outv[4+o*3+2] = vz*gt;
    }
    store_packed16(g_xb, n, outv);
}

// Layer 2: paths 2..6
__global__ void k_edge2() {
    __shared__ __align__(16) float st[NBINS * 20];
    for (int i = threadIdx.x; i < NBINS * 5; i += 256)
        ((float4*)st)[i] = ((const float4*)g_tab2)[i];
    __syncthreads();

    int pbase = blockIdx.x * (PB_CHUNKS * 256) + threadIdx.x;
#pragma unroll 1
    for (int c = 0; c < PB_CHUNKS; c++) {
        int P = pbase + c * 256;
        int e0 = 2 * P, e1 = 2 * P + 1;
        int r0 = g_rs[e0], r1 = g_rs[e1];
        float4 recA = g_rec[e0], recB = g_rec[e1];
        int sA, sB; float dA, uxA, uyA, uzA, dB, uxB, uyB, uzB;
        unpack_rec(recA, sA, dA, uxA, uyA, uzA);
        unpack_rec(recB, sB, dB, uxB, uyB, uzB);
        bool split = (r0 != r1);
        SEG_SETUP_R(r1);
        int binA, binB; float frA, frB;
        bin_of(dA, binA, frA);
        bin_of(dB, binB, frB);

        float vA[16], vB[16];
        load_packed16(g_xb, sA, vA);
        load_packed16(g_xb, sB, vB);
        float* xsA = vA; float* x1A = vA + 4;
        float* xsB = vB; float* x1B = vB + 4;

        float RA[4], RB[4];
        // p00_0 -> b0[0:4]
        lerp4(st, 20, binA, frA, 0, RA);
        lerp4(st, 20, binB, frB, 0, RB);
        {
            float wA[4], wB[4];
#pragma unroll
            for (int cc = 0; cc < 4; cc++) { wA[cc]=RA[cc]*xsA[cc]; wB[cc]=RB[cc]*xsB[cc]; }
            PAIR_EMIT(wA, wB, &g_b0[r0*8], &g_b0[r1*8]);
        }
        // p11_0 -> b0[4:8]
        lerp4(st, 20, binA, frA, 12, RA);
        lerp4(st, 20, binB, frB, 12, RB);
        {
            float wA[4], wB[4];
            wA[0] = RA[0]*INV_SQRT3*(x1A[0]*uxA + x1A[1]*uyA + x1A[2]*uzA);
            wA[1] = RA[1]*INV_SQRT3*(x1A[3]*uxA + x1A[4]*uyA + x1A[5]*uzA);
            wA[2] = RA[2]*INV_SQRT3*(x1A[6]*uxA + x1A[7]*uyA + x1A[8]*uzA);
            wA[3] = RA[3]*INV_SQRT3*(x1A[9]*uxA + x1A[10]*uyA + x1A[11]*uzA);
            wB[0] = RB[0]*INV_SQRT3*(x1B[0]*uxB + x1B[1]*uyB + x1B[2]*uzB);
            wB[1] = RB[1]*INV_SQRT3*(x1B[3]*uxB + x1B[4]*uyB + x1B[5]*uzB);
            wB[2] = RB[2]*INV_SQRT3*(x1B[6]*uxB + x1B[7]*uyB + x1B[8]*uzB);
            wB[3] = RB[3]*INV_SQRT3*(x1B[9]*uxB + x1B[10]*uyB + x1B[11]*uzB);
            PAIR_EMIT(wA, wB, &g_b0[r0*8+4], &g_b0[r1*8+4]);
        }
        float* b1A = &g_b1[r0*36];
        float* b1B = &g_b1[r1*36];
        // p01_1
        lerp4(st, 20, binA, frA, 4, RA);
        lerp4(st, 20, binB, frB, 4, RB);
        {
            float mA[12], mB[12];
#pragma unroll
            for (int cc = 0; cc < 4; cc++) {
                float tA = RA[cc]*xsA[cc], tB = RB[cc]*xsB[cc];
                mA[cc*3+0]=tA*uxA; mA[cc*3+1]=tA*uyA; mA[cc*3+2]=tA*uzA;
                mB[cc*3+0]=tB*uxB; mB[cc*3+1]=tB*uyB; mB[cc*3+2]=tB*uzB;
            }
            PAIR_EMIT(mA+0, mB+0, b1A+0, b1B+0);
            PAIR_EMIT(mA+4, mB+4, b1A+4, b1B+4);
            PAIR_EMIT(mA+8, mB+8, b1A+8, b1B+8);
        }
        // p10_1
        lerp4(st, 20, binA, frA, 8, RA);
        lerp4(st, 20, binB, frB, 8, RB);
        {
            float mA[12], mB[12];
#pragma unroll
            for (int cc = 0; cc < 4; cc++) {
                mA[cc*3+0]=RA[cc]*x1A[cc*3+0]; mA[cc*3+1]=RA[cc]*x1A[cc*3+1]; mA[cc*3+2]=RA[cc]*x1A[cc*3+2];
                mB[cc*3+0]=RB[cc]*x1B[cc*3+0]; mB[cc*3+1]=RB[cc]*x1B[cc*3+1]; mB[cc*3+2]=RB[cc]*x1B[cc*3+2];
            }
            PAIR_EMIT(mA+0, mB+0, b1A+12, b1B+12);
            PAIR_EMIT(mA+4, mB+4, b1A+16, b1B+16);
            PAIR_EMIT(mA+8, mB+8, b1A+20, b1B+20);
        }
        // p11_1
        lerp4(st, 20, binA, frA, 16, RA);
        lerp4(st, 20, binB, frB, 16, RB);
        {
            float mA[12], mB[12];
#pragma unroll
            for (int cc = 0; cc < 4; cc++) {
                float ax = x1A[cc*3+0], ay = x1A[cc*3+1], az = x1A[cc*3+2];
                float tA = RA[cc] * INV_SQRT2;
                mA[cc*3+0]=tA*(ay*uzA - az*uyA);
                mA[cc*3+1]=tA*(az*uxA - ax*uzA);
                mA[cc*3+2]=tA*(ax*uyA - ay*uxA);
                float bx = x1B[cc*3+0], by = x1B[cc*3+1], bz = x1B[cc*3+2];
                float tB = RB[cc] * INV_SQRT2;
                mB[cc*3+0]=tB*(by*uzB - bz*uyB);
                mB[cc*3+1]=tB*(bz*uxB - bx*uzB);
                mB[cc*3+2]=tB*(bx*uyB - by*uxB);
            }
            PAIR_EMIT(mA+0, mB+0, b1A+24, b1B+24);
            PAIR_EMIT(mA+4, mB+4, b1A+28, b1B+28);
            PAIR_EMIT(mA+8, mB+8, b1A+32, b1B+32);
        }
    }
}

// node update 2: si3 + gate -> packed fp16
__global__ void k_node2(const float* __restrict__ w30, const float* __restrict__ w31) {
    int n = blockIdx.x * blockDim.x + threadIdx.x;
    if (n >= N_NODES) return;
    float b0[8];
    {
        float4 t0 = ((const float4*)g_b0)[n*2+0];
        float4 t1 = ((const float4*)g_b0)[n*2+1];
        b0[0]=t0.x; b0[1]=t0.y; b0[2]=t0.z; b0[3]=t0.w;
        b0[4]=t1.x; b0[5]=t1.y; b0[6]=t1.z; b0[7]=t1.w;
    }
    float outv[16];
#pragma unroll
    for (int o = 0; o < 4; o++) {
        float sacc = 0.f;
#pragma unroll
        for (int i = 0; i < 8; i++) sacc = fmaf(__ldg(&w30[o*8+i]), b0[i], sacc);
        outv[o] = sacc * sigmoidf(sacc);
    }
    float b1[36];
#pragma unroll
    for (int q = 0; q < 9; q++) {
        float4 t = ((const float4*)g_b1)[n*9+q];
        b1[q*4+0]=t.x; b1[q*4+1]=t.y; b1[q*4+2]=t.z; b1[q*4+3]=t.w;
    }
#pragma unroll
    for (int o = 0; o < 4; o++) {
        float vx = 0.f, vy = 0.f, vz = 0.f;
#pragma unroll
        for (int i = 0; i < 12; i++) {
            float w = __ldg(&w31[o*12+i]);
            vx = fmaf(w, b1[i*3+0], vx);
            vy = fmaf(w, b1[i*3+1], vy);
            vz = fmaf(w, b1[i*3+2], vz);
        }
        float nrm = sqrtf(vx*vx + vy*vy + vz*vz);
        float gt = sigmoidf(nrm);
        outv[4+o*3+0]=vx*gt; outv[4+o*3+1]=vy*gt; outv[4+o*3+2]=vz*gt;
    }
    store_packed16(g_xc, n, outv);
}

// Layer 3: paths 7,8
__global__ void k_edge3() {
    __shared__ __align__(16) float st[NBINS * 8];
    for (int i = threadIdx.x; i < NBINS * 2; i += 256)
        ((float4*)st)[i] = ((const float4*)g_tab3)[i];
    __syncthreads();

    int pbase = blockIdx.x * (PB_CHUNKS * 256) + threadIdx.x;
#pragma unroll 1
    for (int c = 0; c < PB_CHUNKS; c++) {
        int P = pbase + c * 256;
        int e0 = 2 * P, e1 = 2 * P + 1;
        int r0 = g_rs[e0], r1 = g_rs[e1];
        float4 recA = g_rec[e0], recB = g_rec[e1];
        int sA, sB; float dA, uxA, uyA, uzA, dB, uxB, uyB, uzB;
        unpack_rec(recA, sA, dA, uxA, uyA, uzA);
        unpack_rec(recB, sB, dB, uxB, uyB, uzB);
        bool split = (r0 != r1);
        SEG_SETUP_R(r1);
        int binA, binB; float frA, frB;
        bin_of(dA, binA, frA);
        bin_of(dB, binB, frB);

        float vA[16], vB[16];
        load_packed16(g_xc, sA, vA);
        load_packed16(g_xc, sB, vB);

        float RA[4], RB[4];
        lerp4(st, 8, binA, frA, 0, RA);
        lerp4(st, 8, binB, frB, 0, RB);
        {
            float wA[4], wB[4];
#pragma unroll
            for (int cc = 0; cc < 4; cc++) { wA[cc]=RA[cc]*vA[cc]; wB[cc]=RB[cc]*vB[cc]; }
            PAIR_EMIT(wA, wB, &g_c0[r0*8], &g_c0[r1*8]);
        }
        lerp4(st, 8, binA, frA, 4, RA);
        lerp4(st, 8, binB, frB, 4, RB);
        {
            const float* x1A = vA + 4;
            const float* x1B = vB + 4;
            float wA[4], wB[4];
            wA[0] = RA[0]*INV_SQRT3*(x1A[0]*uxA + x1A[1]*uyA + x1A[2]*uzA);
            wA[1] = RA[1]*INV_SQRT3*(x1A[3]*uxA + x1A[4]*uyA + x1A[5]*uzA);
            wA[2] = RA[2]*INV_SQRT3*(x1A[6]*uxA + x1A[7]*uyA + x1A[8]*uzA);
            wA[3] = RA[3]*INV_SQRT3*(x1A[9]*uxA + x1A[10]*uyA + x1A[11]*uzA);
            wB[0] = RB[0]*INV_SQRT3*(x1B[0]*uxB + x1B[1]*uyB + x1B[2]*uzB);
            wB[1] = RB[1]*INV_SQRT3*(x1B[3]*uxB + x1B[4]*uyB + x1B[5]*uzB);
            wB[2] = RB[2]*INV_SQRT3*(x1B[6]*uxB + x1B[7]*uyB + x1B[8]*uzB);
            wB[3] = RB[3]*INV_SQRT3*(x1B[9]*uxB + x1B[10]*uyB + x1B[11]*uzB);
            PAIR_EMIT(wA, wB, &g_c0[r0*8+4], &g_c0[r1*8+4]);
        }
    }
}

// readout
__global__ void k_final(const float* __restrict__ w4, const float* __restrict__ wout,
                        float* __restrict__ out) {
    int gw = (blockIdx.x * blockDim.x + threadIdx.x) >> 5;
    int lane = threadIdx.x & 31;
    if (gw >= N_GRAPH) return;
    int n = gw * NPG + lane;
    float c0[8];
    {
        float4 t0 = ((const float4*)g_c0)[n*2+0];
        float4 t1 = ((const float4*)g_c0)[n*2+1];
        c0[0]=t0.x; c0[1]=t0.y; c0[2]=t0.z; c0[3]=t0.w;
        c0[4]=t1.x; c0[5]=t1.y; c0[6]=t1.z; c0[7]=t1.w;
    }
    float f[4];
#pragma unroll
    for (int o = 0; o < 4; o++) {
        float sacc = 0.f;
#pragma unroll
        for (int i = 0; i < 8; i++) sacc = fmaf(__ldg(&w4[o*8+i]), c0[i], sacc);
        f[o] = sacc * sigmoidf(sacc);
    }
#pragma unroll
    for (int o = 0; o < 4; o++) {
#pragma unroll
        for (int off = 16; off > 0; off >>= 1)
            f[o] += __shfl_xor_sync(FULLM, f[o], off);
    }
    if (lane < 8) {
        float acc = 0.f;
#pragma unroll
        for (int o = 0; o < 4; o++) acc = fmaf(__ldg(&wout[lane*4+o]), f[o], acc);
        out[gw*8 + lane] = acc;
    }
}

// ---------------- launch ----------------------------------------------------
extern "C" void kernel_launch(void* const* d_in, const int* in_sizes, int n_in,
                              void* d_out, int out_size) {
    const float* pos   = (const float*)d_in[0];
    const float* nf    = (const float*)d_in[1];
    const float* w_si1 = (const float*)d_in[2];
    const float* w20   = (const float*)d_in[3];
    const float* w21   = (const float*)d_in[4];
    const float* w30   = (const float*)d_in[5];
    const float* w31   = (const float*)d_in[6];
    const float* w4    = (const float*)d_in[7];
    const float* wout  = (const float*)d_in[8];
    const float* rw1   = (const float*)d_in[9];
    const float* rb1   = (const float*)d_in[10];
    const float* rw2   = (const float*)d_in[11];
    const float* rb2   = (const float*)d_in[12];
    const int*   snd   = (const int*)d_in[13];
    const int*   rcv   = (const int*)d_in[14];
    float* out = (float*)d_out;

    const int TB = 256;
    k_init   <<<2048, TB>>>();
    k_pos4   <<<N_NODES/TB, TB>>>(pos);
    k_table  <<<2, TB>>>(rw1, rb1, rw2, rb2);
    k_hist   <<<N_EDGES/4/TB, TB>>>(rcv);
    k_scanA  <<<256, 256>>>();
    k_scanB  <<<1, 256>>>();
    k_scanC  <<<256, 256>>>();
    k_fill   <<<N_NODES/256, 256>>>();
    k_scatter<<<N_EDGES/TB, TB>>>(snd, rcv);
    k_edge1  <<<PB_BLOCKS, TB>>>(nf, w_si1);
    k_node1  <<<N_NODES/TB, TB>>>(w20, w21);
    k_edge2  <<<PB_BLOCKS, TB>>>();
    k_node2  <<<N_NODES/TB, TB>>>(w30, w31);
    k_edge3  <<<PB_BLOCKS, TB>>>();
    k_final  <<<(N_GRAPH * 32)/TB, TB>>>(w4, wout, out);
}

// round 17
// speedup vs baseline: 1.0379x; 1.0152x over previous
#include <cuda_runtime.h>
#include <cuda_fp16.h>
#include <cstdint>

#define N_GRAPH   4096
#define NPG       32
#define N_NODES   (N_GRAPH * NPG)      // 131072
#define N_EDGES   (N_NODES * 16)       // 2097152
#define N_PAIRS   (N_EDGES / 2)        // 1048576
#define INV_SQRT3 0.57735026918962576451f
#define INV_SQRT2 0.70710678118654752440f
#define FULLM     0xFFFFFFFFu

#define NBINS     512
#define INV_DELTA 100.0f               // Δ = 0.01, domain [0, 5.11]

#define PB_BLOCKS 2048                 // pairs: 2048 x 2 chunks x 256
#define PB_CHUNKS 2

// ---------------- scratch (static device arrays) -----------------------------
__device__ int   g_cnt[N_NODES];
__device__ int   g_off[N_NODES + 1];
__device__ int   g_cur[N_NODES];
__device__ int   g_bs [256];
__device__ __align__(16) int g_rs [N_EDGES];      // receiver per sorted slot
__device__ __align__(16) float4 g_rec[N_EDGES];   // {dist, s_bits, h2(ux,uy), h2(uz,0)}
__device__ __align__(16) float4 g_pos4[N_NODES];  // padded positions

// radial tables
__device__ __align__(16) float g_tab1[NBINS * 8];   // R0[4] R1[4]
__device__ __align__(16) float g_tab2[NBINS * 20];  // R2..R6
__device__ __align__(16) float g_tab3[NBINS * 8];   // R7[4] R8[4]

__device__ __align__(16) float g_a0 [N_NODES * 4];
__device__ __align__(16) float g_a1 [N_NODES * 12];
__device__ __align__(16) __half g_xb[N_NODES * 16];
__device__ __align__(16) float g_b0 [N_NODES * 8];
__device__ __align__(16) float g_b1 [N_NODES * 36];
__device__ __align__(16) __half g_xc[N_NODES * 16];
__device__ __align__(16) float g_c0 [N_NODES * 8];

// ---------------- helpers ---------------------------------------------------
__device__ __forceinline__ void red4(float* p, float a, float b, float c, float d) {
    asm volatile("red.global.add.v4.f32 [%0], {%1,%2,%3,%4};"
                 :: "l"(p), "f"(a), "f"(b), "f"(c), "f"(d) : "memory");
}

__device__ __forceinline__ float sigmoidf(float x) {
    return 1.0f / (1.0f + __expf(-x));
}

__device__ __forceinline__ void unpack_rec(float4 rec, int& s, float& dist,
                                           float& ux, float& uy, float& uz) {
    dist = rec.x;
    s = __float_as_int(rec.y);
    __half2 xy = *reinterpret_cast<__half2*>(&rec.z);
    __half2 zp = *reinterpret_cast<__half2*>(&rec.w);
    float2 f = __half22float2(xy);
    ux = f.x; uy = f.y;
    uz = __half2float(__low2half(zp));
}

// exact radial (setup only)
__device__ void radial_exact(int p, const float rbf[8], float R[4],
                             const float* w1g, const float* b1g,
                             const float* w2g, const float* b2g) {
    float h[8];
#pragma unroll
    for (int j = 0; j < 8; j++) h[j] = b1g[p*8 + j];
#pragma unroll
    for (int b = 0; b < 8; b++) {
        float rb = rbf[b];
#pragma unroll
        for (int j = 0; j < 8; j++) h[j] = fmaf(rb, w1g[p*64 + b*8 + j], h[j]);
    }
#pragma unroll
    for (int j = 0; j < 8; j++) h[j] = fmaxf(h[j], 0.0f);
#pragma unroll
    for (int c = 0; c < 4; c++) R[c] = b2g[p*4 + c];
#pragma unroll
    for (int j = 0; j < 8; j++) {
        float hj = h[j];
#pragma unroll
        for (int c = 0; c < 4; c++) R[c] = fmaf(hj, w2g[p*32 + j*4 + c], R[c]);
    }
}

__device__ __forceinline__ void lerp4(const float* st, int stride, int bin,
                                      float frac, int off, float R[4]) {
    float4 a = *reinterpret_cast<const float4*>(st + bin * stride + off);
    float4 b = *reinterpret_cast<const float4*>(st + (bin + 1) * stride + off);
    R[0] = fmaf(frac, b.x - a.x, a.x);
    R[1] = fmaf(frac, b.y - a.y, a.y);
    R[2] = fmaf(frac, b.z - a.z, a.z);
    R[3] = fmaf(frac, b.w - a.w, a.w);
}

__device__ __forceinline__ void bin_of(float dist, int& bin, float& frac) {
    float binf = dist * INV_DELTA;
    bin = min((int)binf, NBINS - 2);
    frac = fminf(binf - (float)bin, 1.0f);
}

__device__ __forceinline__ void store_packed16(__half* base, int n, const float* v) {
    uint4 pk[2];
    __half2* hp = reinterpret_cast<__half2*>(pk);
#pragma unroll
    for (int i = 0; i < 8; i++) hp[i] = __floats2half2_rn(v[2*i], v[2*i+1]);
    reinterpret_cast<uint4*>(base)[2*n+0] = pk[0];
    reinterpret_cast<uint4*>(base)[2*n+1] = pk[1];
}

__device__ __forceinline__ void load_packed16(const __half* base, int n, float* v) {
    uint4 pk[2];
    pk[0] = reinterpret_cast<const uint4*>(base)[2*n+0];
    pk[1] = reinterpret_cast<const uint4*>(base)[2*n+1];
    const __half2* hp = reinterpret_cast<const __half2*>(pk);
#pragma unroll
    for (int i = 0; i < 8; i++) {
        float2 f = __half22float2(hp[i]);
        v[2*i] = f.x; v[2*i+1] = f.y;
    }
}

// segmented warp sum keyed by tail receiver
__device__ __forceinline__ void segred4(float v0, float v1, float v2, float v3,
                                        const bool p[5], bool head, float* addr) {
#pragma unroll
    for (int i = 0, off = 1; i < 5; i++, off <<= 1) {
        float t0 = __shfl_down_sync(FULLM, v0, off);
        float t1 = __shfl_down_sync(FULLM, v1, off);
        float t2 = __shfl_down_sync(FULLM, v2, off);
        float t3 = __shfl_down_sync(FULLM, v3, off);
        if (p[i]) { v0 += t0; v1 += t1; v2 += t2; v3 += t3; }
    }
    if (head) red4(addr, v0, v1, v2, v3);
}

// pair emit: direct red4 of prefix on split, segred of combined keyed r1
#define PAIR_EMIT(valA, valB, addr0, addr1)                                    \
    do {                                                                       \
        if (split) red4(addr0, (valA)[0], (valA)[1], (valA)[2], (valA)[3]);    \
        float c0 = split ? (valB)[0] : (valA)[0] + (valB)[0];                  \
        float c1 = split ? (valB)[1] : (valA)[1] + (valB)[1];                  \
        float c2 = split ? (valB)[2] : (valA)[2] + (valB)[2];                  \
        float c3 = split ? (valB)[3] : (valA)[3] + (valB)[3];                  \
        segred4(c0, c1, c2, c3, p, head, addr1);                               \
    } while (0)

#define SEG_SETUP_R(rkey)                                                      \
    int lane = threadIdx.x & 31;                                               \
    uint32_t seg = __match_any_sync(FULLM, rkey);                              \
    bool head = (lane == (__ffs(seg) - 1));                                    \
    bool p[5];                                                                 \
    {                                                                          \
        _Pragma("unroll")                                                      \
        for (int i = 0, off = 1; i < 5; i++, off <<= 1) {                      \
            int ln = lane + off;                                               \
            p[i] = (ln < 32) && ((seg >> ln) & 1u);                            \
        }                                                                      \
    }

// ---------------- setup: zero + pos4 + radial tables (fused) -----------------
__global__ void k_setup(const float* __restrict__ pos,
                        const float* __restrict__ rw1, const float* __restrict__ rb1,
                        const float* __restrict__ rw2, const float* __restrict__ rb2) {
    long i0 = (long)blockIdx.x * blockDim.x + threadIdx.x;
    long stride = (long)gridDim.x * blockDim.x;
    for (long i = i0; i < N_NODES / 4; i += stride)
        ((int4*)g_cnt)[i] = make_int4(0, 0, 0, 0);
    float4 z = make_float4(0.f, 0.f, 0.f, 0.f);
    for (long i = i0; i < N_NODES;     i += stride) ((float4*)g_a0)[i] = z;
    for (long i = i0; i < N_NODES * 3; i += stride) ((float4*)g_a1)[i] = z;
    for (long i = i0; i < N_NODES * 2; i += stride) ((float4*)g_b0)[i] = z;
    for (long i = i0; i < N_NODES * 9; i += stride) ((float4*)g_b1)[i] = z;
    for (long i = i0; i < N_NODES * 2; i += stride) ((float4*)g_c0)[i] = z;
    for (long n = i0; n < N_NODES; n += stride)
        g_pos4[n] = make_float4(pos[3*n+0], pos[3*n+1], pos[3*n+2], 0.f);

    if (i0 < NBINS) {
        int bin = (int)i0;
        float d = (float)bin * (1.0f / INV_DELTA);
        float rbf[8];
#pragma unroll
        for (int b = 0; b < 8; b++) {
            float t = d - 0.5f * (float)b;
            rbf[b] = __expf(-4.0f * t * t);
        }
        float R[4];
        radial_exact(0, rbf, R, rw1, rb1, rw2, rb2);
#pragma unroll
        for (int c = 0; c < 4; c++) g_tab1[bin*8 + c] = R[c];
        radial_exact(1, rbf, R, rw1, rb1, rw2, rb2);
#pragma unroll
        for (int c = 0; c < 4; c++) g_tab1[bin*8 + 4 + c] = R[c];
#pragma unroll
        for (int pth = 2; pth <= 6; pth++) {
            radial_exact(pth, rbf, R, rw1, rb1, rw2, rb2);
#pragma unroll
            for (int c = 0; c < 4; c++) g_tab2[bin*20 + (pth-2)*4 + c] = R[c];
        }
        radial_exact(7, rbf, R, rw1, rb1, rw2, rb2);
#pragma unroll
        for (int c = 0; c < 4; c++) g_tab3[bin*8 + c] = R[c];
        radial_exact(8, rbf, R, rw1, rb1, rw2, rb2);
#pragma unroll
        for (int c = 0; c < 4; c++) g_tab3[bin*8 + 4 + c] = R[c];
    }
}

// ---------------- CSR build --------------------------------------------------
__global__ void k_hist(const int* __restrict__ rcv) {
    int i = blockIdx.x * blockDim.x + threadIdx.x;   // N_EDGES/4 threads
    if (i >= N_EDGES / 4) return;
    int4 rr = ((const int4*)rcv)[i];
    atomicAdd(&g_cnt[rr.x], 1);
    atomicAdd(&g_cnt[rr.y], 1);
    atomicAdd(&g_cnt[rr.z], 1);
    atomicAdd(&g_cnt[rr.w], 1);
}

// local exclusive scan per 512-node block; block totals to g_bs
__global__ void k_scanA() {
    __shared__ int sd[256];
    int b = blockIdx.x, t = threadIdx.x;
    int i = b * 512 + t * 2;
    int e0 = g_cnt[i], e1 = g_cnt[i + 1];
    int s = e0 + e1;
    sd[t] = s;
    __syncthreads();
#pragma unroll
    for (int off = 1; off < 256; off <<= 1) {
        int v = (t >= off) ? sd[t - off] : 0;
        __syncthreads();
        sd[t] += v;
        __syncthreads();
    }
    int incl = sd[t];
    int excl = incl - s;
    g_off[i]     = excl;
    g_off[i + 1] = excl + e0;
    if (t == 255) g_bs[b] = incl;
}

// fused: scan block sums + globalize offsets + fill g_rs for this block's edges
__global__ void k_scanCF() {
    __shared__ int sb[256];
    __shared__ int offs[513];
    int b = blockIdx.x, t = threadIdx.x;
    sb[t] = g_bs[t];
    __syncthreads();
#pragma unroll
    for (int off = 1; off < 256; off <<= 1) {
        int v = (t >= off) ? sb[t - off] : 0;
        __syncthreads();
        sb[t] += v;
        __syncthreads();
    }
    int add = (b > 0) ? sb[b - 1] : 0;   // exclusive prefix for this block
    int i = b * 512 + t * 2;
    int o0 = g_off[i] + add, o1 = g_off[i + 1] + add;
    g_off[i] = o0;  g_off[i + 1] = o1;
    g_cur[i] = o0;  g_cur[i + 1] = o1;
    offs[2*t] = o0; offs[2*t + 1] = o1;
    if (t == 0) offs[512] = sb[b];       // end of this block's edge range
    if (b == 255 && t == 0) g_off[N_NODES] = N_EDGES;
    __syncthreads();

    int beg = offs[0], end = offs[512];
    for (int idx = beg + t; idx < end; idx += 256) {
        int lo = 0, hi = 512;
#pragma unroll
        for (int it = 0; it < 9; it++) {
            int mid = (lo + hi) >> 1;
            if (offs[mid] <= idx) lo = mid; else hi = mid;
        }
        g_rs[idx] = b * 512 + lo;
    }
}

__global__ void k_scatter(const int* __restrict__ snd, const int* __restrict__ rcv) {
    int e = blockIdx.x * blockDim.x + threadIdx.x;
    if (e >= N_EDGES) return;
    int s = snd[e], r = rcv[e];
    float4 ps = g_pos4[s];
    float4 pr = g_pos4[r];
    float dx = pr.x - ps.x, dy = pr.y - ps.y, dz = pr.z - ps.z;
    float dist = sqrtf(dx*dx + dy*dy + dz*dz);
    float inv = 1.0f / fmaxf(dist, 1e-9f);
    int slot = atomicAdd(&g_cur[r], 1);
    __half2 xy = __floats2half2_rn(dx * inv, dy * inv);
    __half2 zp = __floats2half2_rn(dz * inv, 0.f);
    float4 rec;
    rec.x = dist;
    rec.y = __int_as_float(s);
    rec.z = *reinterpret_cast<float*>(&xy);
    rec.w = *reinterpret_cast<float*>(&zp);
    g_rec[slot] = rec;
}

// ---------------- pair edge kernels ------------------------------------------

// Layer 1: paths 0,1
__global__ void k_edge1(const float* __restrict__ nf, const float* __restrict__ wsi1) {
    __shared__ __align__(16) float st[NBINS * 8];
    __shared__ float s1[4];
    for (int i = threadIdx.x; i < NBINS * 2; i += 256)
        ((float4*)st)[i] = ((const float4*)g_tab1)[i];
    if (threadIdx.x < 4) s1[threadIdx.x] = wsi1[threadIdx.x];
    __syncthreads();

    int pbase = blockIdx.x * (PB_CHUNKS * 256) + threadIdx.x;
#pragma unroll 1
    for (int c = 0; c < PB_CHUNKS; c++) {
        int P = pbase + c * 256;
        int e0 = 2 * P, e1 = 2 * P + 1;
        int r0 = g_rs[e0], r1 = g_rs[e1];
        float4 recA = g_rec[e0], recB = g_rec[e1];
        int sA, sB; float dA, uxA, uyA, uzA, dB, uxB, uyB, uzB;
        unpack_rec(recA, sA, dA, uxA, uyA, uzA);
        unpack_rec(recB, sB, dB, uxB, uyB, uzB);
        bool split = (r0 != r1);
        SEG_SETUP_R(r1);
        int binA, binB; float frA, frB;
        bin_of(dA, binA, frA);
        bin_of(dB, binB, frB);

        float R0A[4], R1A[4], R0B[4], R1B[4];
        lerp4(st, 8, binA, frA, 0, R0A);
        lerp4(st, 8, binA, frA, 4, R1A);
        lerp4(st, 8, binB, frB, 0, R0B);
        lerp4(st, 8, binB, frB, 4, R1B);
        float nfA = __ldg(&nf[sA]), nfB = __ldg(&nf[sB]);
        float xsA[4], xsB[4];
#pragma unroll
        for (int cc = 0; cc < 4; cc++) { xsA[cc] = s1[cc]*nfA; xsB[cc] = s1[cc]*nfB; }

        {
            float vA[4], vB[4];
#pragma unroll
            for (int cc = 0; cc < 4; cc++) { vA[cc]=R0A[cc]*xsA[cc]; vB[cc]=R0B[cc]*xsB[cc]; }
            PAIR_EMIT(vA, vB, &g_a0[r0*4], &g_a0[r1*4]);
        }
        float mA[12], mB[12];
#pragma unroll
        for (int cc = 0; cc < 4; cc++) {
            float tA = R1A[cc]*xsA[cc], tB = R1B[cc]*xsB[cc];
            mA[cc*3+0]=tA*uxA; mA[cc*3+1]=tA*uyA; mA[cc*3+2]=tA*uzA;
            mB[cc*3+0]=tB*uxB; mB[cc*3+1]=tB*uyB; mB[cc*3+2]=tB*uzB;
        }
        PAIR_EMIT(mA+0, mB+0, &g_a1[r0*12+0], &g_a1[r1*12+0]);
        PAIR_EMIT(mA+4, mB+4, &g_a1[r0*12+4], &g_a1[r1*12+4]);
        PAIR_EMIT(mA+8, mB+8, &g_a1[r0*12+8], &g_a1[r1*12+8]);
    }
}

// node update 1: si2 + gate -> packed fp16
__global__ void k_node1(const float* __restrict__ w20, const float* __restrict__ w21) {
    int n = blockIdx.x * blockDim.x + threadIdx.x;
    if (n >= N_NODES) return;
    float4 a0 = ((const float4*)g_a0)[n];
    float in0[4] = {a0.x, a0.y, a0.z, a0.w};
    float outv[16];
#pragma unroll
    for (int o = 0; o < 4; o++) {
        float sacc = 0.f;
#pragma unroll
        for (int i = 0; i < 4; i++) sacc = fmaf(__ldg(&w20[o*4+i]), in0[i], sacc);
        outv[o] = sacc * sigmoidf(sacc);
    }
    float a1[12];
    float4 t0 = ((const float4*)g_a1)[n*3+0];
    float4 t1 = ((const float4*)g_a1)[n*3+1];
    float4 t2 = ((const float4*)g_a1)[n*3+2];
    a1[0]=t0.x; a1[1]=t0.y; a1[2]=t0.z; a1[3]=t0.w;
    a1[4]=t1.x; a1[5]=t1.y; a1[6]=t1.z; a1[7]=t1.w;
    a1[8]=t2.x; a1[9]=t2.y; a1[10]=t2.z; a1[11]=t2.w;
#pragma unroll
    for (int o = 0; o < 4; o++) {
        float vx = 0.f, vy = 0.f, vz = 0.f;
#pragma unroll
        for (int i = 0; i < 4; i++) {
            float w = __ldg(&w21[o*4+i]);
            vx = fmaf(w, a1[i*3+0], vx);
            vy = fmaf(w, a1[i*3+1], vy);
            vz = fmaf(w, a1[i*3+2], vz);
        }
        float nrm = sqrtf(vx*vx + vy*vy + vz*vz);
        float gt = sigmoidf(nrm);
        outv[4+o*3+0] = vx*gt; outv[4+o*3+1] = vy*gt; outv[4+o*3+2] = vz*gt;
    }
    store_packed16(g_xb, n, outv);
}

// Layer 2: paths 2..6
__global__ void k_edge2() {
    __shared__ __align__(16) float st[NBINS * 20];
    for (int i = threadIdx.x; i < NBINS * 5; i += 256)
        ((float4*)st)[i] = ((const float4*)g_tab2)[i];
    __syncthreads();

    int pbase = blockIdx.x * (PB_CHUNKS * 256) + threadIdx.x;
#pragma unroll 1
    for (int c = 0; c < PB_CHUNKS; c++) {
        int P = pbase + c * 256;
        int e0 = 2 * P, e1 = 2 * P + 1;
        int r0 = g_rs[e0], r1 = g_rs[e1];
        float4 recA = g_rec[e0], recB = g_rec[e1];
        int sA, sB; float dA, uxA, uyA, uzA, dB, uxB, uyB, uzB;
        unpack_rec(recA, sA, dA, uxA, uyA, uzA);
        unpack_rec(recB, sB, dB, uxB, uyB, uzB);
        bool split = (r0 != r1);
        SEG_SETUP_R(r1);
        int binA, binB; float frA, frB;
        bin_of(dA, binA, frA);
        bin_of(dB, binB, frB);

        float vA[16], vB[16];
        load_packed16(g_xb, sA, vA);
        load_packed16(g_xb, sB, vB);
        float* xsA = vA; float* x1A = vA + 4;
        float* xsB = vB; float* x1B = vB + 4;

        float RA[4], RB[4];
        // p00_0 -> b0[0:4]
        lerp4(st, 20, binA, frA, 0, RA);
        lerp4(st, 20, binB, frB, 0, RB);
        {
            float wA[4], wB[4];
#pragma unroll
            for (int cc = 0; cc < 4; cc++) { wA[cc]=RA[cc]*xsA[cc]; wB[cc]=RB[cc]*xsB[cc]; }
            PAIR_EMIT(wA, wB, &g_b0[r0*8], &g_b0[r1*8]);
        }
        // p11_0 -> b0[4:8]
        lerp4(st, 20, binA, frA, 12, RA);
        lerp4(st, 20, binB, frB, 12, RB);
        {
            float wA[4], wB[4];
            wA[0] = RA[0]*INV_SQRT3*(x1A[0]*uxA + x1A[1]*uyA + x1A[2]*uzA);
            wA[1] = RA[1]*INV_SQRT3*(x1A[3]*uxA + x1A[4]*uyA + x1A[5]*uzA);
            wA[2] = RA[2]*INV_SQRT3*(x1A[6]*uxA + x1A[7]*uyA + x1A[8]*uzA);
            wA[3] = RA[3]*INV_SQRT3*(x1A[9]*uxA + x1A[10]*uyA + x1A[11]*uzA);
            wB[0] = RB[0]*INV_SQRT3*(x1B[0]*uxB + x1B[1]*uyB + x1B[2]*uzB);
            wB[1] = RB[1]*INV_SQRT3*(x1B[3]*uxB + x1B[4]*uyB + x1B[5]*uzB);
            wB[2] = RB[2]*INV_SQRT3*(x1B[6]*uxB + x1B[7]*uyB + x1B[8]*uzB);
            wB[3] = RB[3]*INV_SQRT3*(x1B[9]*uxB + x1B[10]*uyB + x1B[11]*uzB);
            PAIR_EMIT(wA, wB, &g_b0[r0*8+4], &g_b0[r1*8+4]);
        }
        float* b1A = &g_b1[r0*36];
        float* b1B = &g_b1[r1*36];
        // p01_1
        lerp4(st, 20, binA, frA, 4, RA);
        lerp4(st, 20, binB, frB, 4, RB);
        {
            float mA[12], mB[12];
#pragma unroll
            for (int cc = 0; cc < 4; cc++) {
                float tA = RA[cc]*xsA[cc], tB = RB[cc]*xsB[cc];
                mA[cc*3+0]=tA*uxA; mA[cc*3+1]=tA*uyA; mA[cc*3+2]=tA*uzA;
                mB[cc*3+0]=tB*uxB; mB[cc*3+1]=tB*uyB; mB[cc*3+2]=tB*uzB;
            }
            PAIR_EMIT(mA+0, mB+0, b1A+0, b1B+0);
            PAIR_EMIT(mA+4, mB+4, b1A+4, b1B+4);
            PAIR_EMIT(mA+8, mB+8, b1A+8, b1B+8);
        }
        // p10_1
        lerp4(st, 20, binA, frA, 8, RA);
        lerp4(st, 20, binB, frB, 8, RB);
        {
            float mA[12], mB[12];
#pragma unroll
            for (int cc = 0; cc < 4; cc++) {
                mA[cc*3+0]=RA[cc]*x1A[cc*3+0]; mA[cc*3+1]=RA[cc]*x1A[cc*3+1]; mA[cc*3+2]=RA[cc]*x1A[cc*3+2];
                mB[cc*3+0]=RB[cc]*x1B[cc*3+0]; mB[cc*3+1]=RB[cc]*x1B[cc*3+1]; mB[cc*3+2]=RB[cc]*x1B[cc*3+2];
            }
            PAIR_EMIT(mA+0, mB+0, b1A+12, b1B+12);
            PAIR_EMIT(mA+4, mB+4, b1A+16, b1B+16);
            PAIR_EMIT(mA+8, mB+8, b1A+20, b1B+20);
        }
        // p11_1
        lerp4(st, 20, binA, frA, 16, RA);
        lerp4(st, 20, binB, frB, 16, RB);
        {
            float mA[12], mB[12];
#pragma unroll
            for (int cc = 0; cc < 4; cc++) {
                float ax = x1A[cc*3+0], ay = x1A[cc*3+1], az = x1A[cc*3+2];
                float tA = RA[cc] * INV_SQRT2;
                mA[cc*3+0]=tA*(ay*uzA - az*uyA);
                mA[cc*3+1]=tA*(az*uxA - ax*uzA);
                mA[cc*3+2]=tA*(ax*uyA - ay*uxA);
                float bx = x1B[cc*3+0], by = x1B[cc*3+1], bz = x1B[cc*3+2];
                float tB = RB[cc] * INV_SQRT2;
                mB[cc*3+0]=tB*(by*uzB - bz*uyB);
                mB[cc*3+1]=tB*(bz*uxB - bx*uzB);
                mB[cc*3+2]=tB*(bx*uyB - by*uxB);
            }
            PAIR_EMIT(mA+0, mB+0, b1A+24, b1B+24);
            PAIR_EMIT(mA+4, mB+4, b1A+28, b1B+28);
            PAIR_EMIT(mA+8, mB+8, b1A+32, b1B+32);
        }
    }
}

// node update 2: si3 + gate -> packed fp16
__global__ void k_node2(const float* __restrict__ w30, const float* __restrict__ w31) {
    int n = blockIdx.x * blockDim.x + threadIdx.x;
    if (n >= N_NODES) return;
    float b0[8];
    {
        float4 t0 = ((const float4*)g_b0)[n*2+0];
        float4 t1 = ((const float4*)g_b0)[n*2+1];
        b0[0]=t0.x; b0[1]=t0.y; b0[2]=t0.z; b0[3]=t0.w;
        b0[4]=t1.x; b0[5]=t1.y; b0[6]=t1.z; b0[7]=t1.w;
    }
    float outv[16];
#pragma unroll
    for (int o = 0; o < 4; o++) {
        float sacc = 0.f;
#pragma unroll
        for (int i = 0; i < 8; i++) sacc = fmaf(__ldg(&w30[o*8+i]), b0[i], sacc);
        outv[o] = sacc * sigmoidf(sacc);
    }
    float b1[36];
#pragma unroll
    for (int q = 0; q < 9; q++) {
        float4 t = ((const float4*)g_b1)[n*9+q];
        b1[q*4+0]=t.x; b1[q*4+1]=t.y; b1[q*4+2]=t.z; b1[q*4+3]=t.w;
    }
#pragma unroll
    for (int o = 0; o < 4; o++) {
        float vx = 0.f, vy = 0.f, vz = 0.f;
#pragma unroll
        for (int i = 0; i < 12; i++) {
            float w = __ldg(&w31[o*12+i]);
            vx = fmaf(w, b1[i*3+0], vx);
            vy = fmaf(w, b1[i*3+1], vy);
            vz = fmaf(w, b1[i*3+2], vz);
        }
        float nrm = sqrtf(vx*vx + vy*vy + vz*vz);
        float gt = sigmoidf(nrm);
        outv[4+o*3+0]=vx*gt; outv[4+o*3+1]=vy*gt; outv[4+o*3+2]=vz*gt;
    }
    store_packed16(g_xc, n, outv);
}

// Layer 3: paths 7,8
__global__ void k_edge3() {
    __shared__ __align__(16) float st[NBINS * 8];
    for (int i = threadIdx.x; i < NBINS * 2; i += 256)
        ((float4*)st)[i] = ((const float4*)g_tab3)[i];
    __syncthreads();

    int pbase = blockIdx.x * (PB_CHUNKS * 256) + threadIdx.x;
#pragma unroll 1
    for (int c = 0; c < PB_CHUNKS; c++) {
        int P = pbase + c * 256;
        int e0 = 2 * P, e1 = 2 * P + 1;
        int r0 = g_rs[e0], r1 = g_rs[e1];
        float4 recA = g_rec[e0], recB = g_rec[e1];
        int sA, sB; float dA, uxA, uyA, uzA, dB, uxB, uyB, uzB;
        unpack_rec(recA, sA, dA, uxA, uyA, uzA);
        unpack_rec(recB, sB, dB, uxB, uyB, uzB);
        bool split = (r0 != r1);
        SEG_SETUP_R(r1);
        int binA, binB; float frA, frB;
        bin_of(dA, binA, frA);
        bin_of(dB, binB, frB);

        float vA[16], vB[16];
        load_packed16(g_xc, sA, vA);
        load_packed16(g_xc, sB, vB);

        float RA[4], RB[4];
        lerp4(st, 8, binA, frA, 0, RA);
        lerp4(st, 8, binB, frB, 0, RB);
        {
            float wA[4], wB[4];
#pragma unroll
            for (int cc = 0; cc < 4; cc++) { wA[cc]=RA[cc]*vA[cc]; wB[cc]=RB[cc]*vB[cc]; }
            PAIR_EMIT(wA, wB, &g_c0[r0*8], &g_c0[r1*8]);
        }
        lerp4(st, 8, binA, frA, 4, RA);
        lerp4(st, 8, binB, frB, 4, RB);
        {
            const float* x1A = vA + 4;
            const float* x1B = vB + 4;
            float wA[4], wB[4];
            wA[0] = RA[0]*INV_SQRT3*(x1A[0]*uxA + x1A[1]*uyA + x1A[2]*uzA);
            wA[1] = RA[1]*INV_SQRT3*(x1A[3]*uxA + x1A[4]*uyA + x1A[5]*uzA);
            wA[2] = RA[2]*INV_SQRT3*(x1A[6]*uxA + x1A[7]*uyA + x1A[8]*uzA);
            wA[3] = RA[3]*INV_SQRT3*(x1A[9]*uxA + x1A[10]*uyA + x1A[11]*uzA);
            wB[0] = RB[0]*INV_SQRT3*(x1B[0]*uxB + x1B[1]*uyB + x1B[2]*uzB);
            wB[1] = RB[1]*INV_SQRT3*(x1B[3]*uxB + x1B[4]*uyB + x1B[5]*uzB);
            wB[2] = RB[2]*INV_SQRT3*(x1B[6]*uxB + x1B[7]*uyB + x1B[8]*uzB);
            wB[3] = RB[3]*INV_SQRT3*(x1B[9]*uxB + x1B[10]*uyB + x1B[11]*uzB);
            PAIR_EMIT(wA, wB, &g_c0[r0*8+4], &g_c0[r1*8+4]);
        }
    }
}

// readout
__global__ void k_final(const float* __restrict__ w4, const float* __restrict__ wout,
                        float* __restrict__ out) {
    int gw = (blockIdx.x * blockDim.x + threadIdx.x) >> 5;
    int lane = threadIdx.x & 31;
    if (gw >= N_GRAPH) return;
    int n = gw * NPG + lane;
    float c0[8];
    {
        float4 t0 = ((const float4*)g_c0)[n*2+0];
        float4 t1 = ((const float4*)g_c0)[n*2+1];
        c0[0]=t0.x; c0[1]=t0.y; c0[2]=t0.z; c0[3]=t0.w;
        c0[4]=t1.x; c0[5]=t1.y; c0[6]=t1.z; c0[7]=t1.w;
    }
    float f[4];
#pragma unroll
    for (int o = 0; o < 4; o++) {
        float sacc = 0.f;
#pragma unroll
        for (int i = 0; i < 8; i++) sacc = fmaf(__ldg(&w4[o*8+i]), c0[i], sacc);
        f[o] = sacc * sigmoidf(sacc);
    }
#pragma unroll
    for (int o = 0; o < 4; o++) {
#pragma unroll
        for (int off = 16; off > 0; off >>= 1)
            f[o] += __shfl_xor_sync(FULLM, f[o], off);
    }
    if (lane < 8) {
        float acc = 0.f;
#pragma unroll
        for (int o = 0; o < 4; o++) acc = fmaf(__ldg(&wout[lane*4+o]), f[o], acc);
        out[gw*8 + lane] = acc;
    }
}

// ---------------- launch ----------------------------------------------------
extern "C" void kernel_launch(void* const* d_in, const int* in_sizes, int n_in,
                              void* d_out, int out_size) {
    const float* pos   = (const float*)d_in[0];
    const float* nf    = (const float*)d_in[1];
    const float* w_si1 = (const float*)d_in[2];
    const float* w20   = (const float*)d_in[3];
    const float* w21   = (const float*)d_in[4];
    const float* w30   = (const float*)d_in[5];
    const float* w31   = (const float*)d_in[6];
    const float* w4    = (const float*)d_in[7];
    const float* wout  = (const float*)d_in[8];
    const float* rw1   = (const float*)d_in[9];
    const float* rb1   = (const float*)d_in[10];
    const float* rw2   = (const float*)d_in[11];
    const float* rb2   = (const float*)d_in[12];
    const int*   snd   = (const int*)d_in[13];
    const int*   rcv   = (const int*)d_in[14];
    float* out = (float*)d_out;

    const int TB = 256;
    k_setup  <<<2048, TB>>>(pos, rw1, rb1, rw2, rb2);
    k_hist   <<<N_EDGES/4/TB, TB>>>(rcv);
    k_scanA  <<<256, 256>>>();
    k_scanCF <<<256, 256>>>();
    k_scatter<<<N_EDGES/TB, TB>>>(snd, rcv);
    k_edge1  <<<PB_BLOCKS, TB>>>(nf, w_si1);
    k_node1  <<<N_NODES/TB, TB>>>(w20, w21);
    k_edge2  <<<PB_BLOCKS, TB>>>();
    k_node2  <<<N_NODES/TB, TB>>>(w30, w31);
    k_edge3  <<<PB_BLOCKS, TB>>>();
    k_final  <<<(N_GRAPH * 32)/TB, TB>>>(w4, wout, out);
}